// round 12
// baseline (speedup 1.0000x reference)
#include <cuda_runtime.h>
#include <cuda_bf16.h>
#include <math.h>
#include <stdint.h>
#include <stddef.h>

#define B_ 64
#define L_ 512
#define C_ 321
#define BC 20544            // B_*C_
#define PRED_ 96
#define LP 520              // L + STRIDE
#define NB1 1284            // BC/16 blocks (k1b/k4/k6)
#define CNT_BN 657408.0f    // BC*32
#define EPS_ 1e-5f

// ---------------- scratch (__device__ globals; no runtime allocation) ----------------
static __device__ float g_s[(size_t)BC * LP];        // seasonal, padded
static __device__ float g_trend[(size_t)BC * L_];    // trend rows [bc][L]
static __device__ float g_mean[BC];
static __device__ float g_std[BC];
static __device__ float g_h[(size_t)BC * 2048];      // h1 = gelu(fc1), layout [bc][j(32)][n(64)]
static __device__ float g_y[(size_t)BC * 1024];      // post-LN y [bc][1024]
static __device__ float g_pool[(size_t)BC * 64];     // sp.mean(-1)
static __device__ float g_w[(size_t)BC * 64];        // gating sigmoid output
static __device__ float g_Wt[1536 * 96];             // folded weights, [k][j]
static __device__ float g_cb[96];                    // folded bias
static __device__ float g_p1s[NB1 * 64];
static __device__ float g_p1q[NB1 * 64];
static __device__ float g_p2s[NB1 * 64];
static __device__ float g_p2q[NB1 * 64];
static __device__ float g_sc1[64], g_bi1[64], g_sc2[64], g_bi2[64];

__device__ __forceinline__ float geluf(float v) {
    return 0.5f * v * (1.0f + erff(v * 0.70710678f));
}
__device__ __forceinline__ float sigf(float v) {
    return 1.0f / (1.0f + expf(-v));
}

// cp.async helpers (LDGSTS)
__device__ __forceinline__ void cpa16(uint32_t d, const float* s) {
    asm volatile("cp.async.ca.shared.global [%0], [%1], 16;\n" :: "r"(d), "l"(s));
}
__device__ __forceinline__ void cp_commit() {
    asm volatile("cp.async.commit_group;\n" ::: "memory");
}

// ---------------- K0: fold fusion layer ----------------
__global__ void k0_fold1(const float* __restrict__ seas_w, const float* __restrict__ fus_w) {
    int idx = blockIdx.x * 256 + threadIdx.x;       // 96*1024
    int j = idx >> 10, m = idx & 1023;
    const float* fw = fus_w + j * 192;
    float a = 0.f;
    #pragma unroll 8
    for (int k = 0; k < 96; k++) a = fmaf(fw[k], seas_w[k * 1024 + m], a);
    g_Wt[m * 96 + j] = a;
}
__global__ void k0_fold2(const float* __restrict__ tr_w, const float* __restrict__ fus_w) {
    int idx = blockIdx.x * 256 + threadIdx.x;       // 96*512
    int j = idx >> 9, m = idx & 511;
    const float* fw = fus_w + j * 192 + 96;
    float a = 0.f;
    #pragma unroll 8
    for (int k = 0; k < 96; k++) a = fmaf(fw[k], tr_w[k * 512 + m], a);
    g_Wt[(1024 + m) * 96 + j] = a;
}
__global__ void k0_cb(const float* __restrict__ fus_w, const float* __restrict__ fus_b,
                      const float* __restrict__ seas_b, const float* __restrict__ tr_b) {
    int j = threadIdx.x;
    float a = fus_b[j];
    for (int k = 0; k < 96; k++) {
        a = fmaf(fus_w[j * 192 + k], seas_b[k], a);
        a = fmaf(fus_w[j * 192 + 96 + k], tr_b[k], a);
    }
    g_cb[j] = a;
}

// ---------------- K1a: RevIN stats + segmented EMA + seasonal/trend + pooled ----------------
__global__ void __launch_bounds__(256) k1a_prep(const float* __restrict__ x,
                                                const float* __restrict__ rev_w,
                                                const float* __restrict__ rev_b) {
    extern __shared__ float sm[];
    float* xb = sm;                 // [512][33]
    float* tb = sm + 512 * 33;      // [512][33]
    __shared__ float red_s[8][33], red_q[8][33], meanb[32], stdb[32];
    __shared__ float segend[8][33], carry[8][33];
    __shared__ float pw[65];
    int b = blockIdx.y;
    int c0 = blockIdx.x * 32;
    int t = threadIdx.x;
    int w = t >> 5, lane = t & 31;
    int c = c0 + lane;
    bool cv = (c < C_);

    if (t == 0) {
        pw[0] = 1.f;
        for (int j = 1; j <= 64; j++) pw[j] = pw[j - 1] * 0.8f;
    }

    float s = 0.f, q = 0.f;
    for (int l = w; l < L_; l += 8) {
        float v = cv ? x[((size_t)b * L_ + l) * C_ + c] : 0.f;
        xb[l * 33 + lane] = v;
        s += v;
        q = fmaf(v, v, q);
    }
    red_s[w][lane] = s; red_q[w][lane] = q;
    __syncthreads();
    if (w == 0) {
        float ss = 0.f, qq = 0.f;
        #pragma unroll
        for (int i = 0; i < 8; i++) { ss += red_s[i][lane]; qq += red_q[i][lane]; }
        float mu = ss * (1.f / (float)L_);
        float v2 = fmaxf(qq - (float)L_ * mu * mu, 0.f);
        float sd = sqrtf(v2 * (1.f / (float)(L_ - 1))) + EPS_;
        meanb[lane] = mu; stdb[lane] = sd;
        if (cv) { int bc = b * C_ + c; g_mean[bc] = mu; g_std[bc] = sd; }
    }
    __syncthreads();
    {
        float rw = cv ? rev_w[c] : 1.f;
        float rb = cv ? rev_b[c] : 0.f;
        float mu = meanb[lane], inv = 1.f / stdb[lane];
        for (int l = w; l < L_; l += 8) {
            float v = xb[l * 33 + lane];
            xb[l * 33 + lane] = fmaf((v - mu) * inv, rw, rb);
        }
    }
    __syncthreads();
    {
        int base = w * 64;
        float cl;
        if (w == 0) {
            cl = xb[lane];
            tb[lane] = cl;
            #pragma unroll 4
            for (int l = 1; l < 64; l++) {
                cl = fmaf(0.8f, cl, 0.2f * xb[l * 33 + lane]);
                tb[l * 33 + lane] = cl;
            }
        } else {
            cl = 0.f;
            #pragma unroll 4
            for (int j = 0; j < 64; j++) {
                int l = base + j;
                cl = fmaf(0.8f, cl, 0.2f * xb[l * 33 + lane]);
                tb[l * 33 + lane] = cl;
            }
        }
        segend[w][lane] = cl;
    }
    __syncthreads();
    if (t < 32) {
        float cacc = segend[0][t];
        carry[1][t] = cacc;
        float q64 = pw[64];
        #pragma unroll
        for (int s2 = 1; s2 <= 6; s2++) {
            cacc = fmaf(q64, cacc, segend[s2][t]);
            carry[s2 + 1][t] = cacc;
        }
    }
    __syncthreads();
    {
        int base = w * 64;
        float cin = (w == 0) ? 0.f : carry[w][lane];
        #pragma unroll 4
        for (int j = 0; j < 64; j++) {
            int l = base + j;
            float tf = fmaf(pw[j + 1], cin, tb[l * 33 + lane]);
            tb[l * 33 + lane] = tf;
            xb[l * 33 + lane] = xb[l * 33 + lane] - tf;
        }
    }
    __syncthreads();
    for (int ci = w; ci < 32; ci += 8) {
        int cc = c0 + ci;
        if (cc >= C_) continue;
        size_t bc = (size_t)b * C_ + cc;
        float* gs = g_s + bc * LP;
        float* gt = g_trend + bc * (size_t)L_;
        for (int l0 = 0; l0 < L_; l0 += 32) {
            gs[l0 + lane] = xb[(l0 + lane) * 33 + ci];
            gt[l0 + lane] = tb[(l0 + lane) * 33 + ci];
        }
        if (lane < 8) gs[L_ + lane] = xb[511 * 33 + ci];
        #pragma unroll
        for (int nn = 0; nn < 2; nn++) {
            int n = 2 * lane + nn;
            float sum = 0.f;
            #pragma unroll
            for (int p = 0; p < 16; p++) {
                int l = n * 8 + p;
                if (l > 511) l = 511;
                sum += xb[l * 33 + ci];
            }
            g_pool[bc * 64 + n] = sum * (1.f / 16.f);
        }
    }
}

// ---------------- K1b: fc1 + gelu -> g_h ([bc][j][n]); bn1 per-n partials ----------------
__global__ void __launch_bounds__(256) k1b_fc1(const float* __restrict__ fc1_w,
                                               const float* __restrict__ fc1_b) {
    __shared__ float s_sm[16 * LP];       // 33280B
    __shared__ float wt[512];             // wt[p*32+j] = fc1_w[j*16+p]
    __shared__ float stage[32 * 65];      // [j][n] padded
    int t = threadIdx.x;
    int w = t >> 5, lane = t & 31;
    size_t bc0 = (size_t)blockIdx.x * 16;
    for (int i = t; i < 512; i += 256) {
        int p = i >> 5, j = i & 31;
        wt[i] = fc1_w[j * 16 + p];
    }
    for (int i = t; i < 16 * LP; i += 256) s_sm[i] = g_s[bc0 * LP + i];
    __syncthreads();
    float wj[16];
    #pragma unroll
    for (int p = 0; p < 16; p++) wj[p] = wt[p * 32 + lane];
    float bj = fc1_b[lane];
    float ps[8], pq[8];
    #pragma unroll
    for (int i = 0; i < 8; i++) { ps[i] = 0.f; pq[i] = 0.f; }

    for (int r = 0; r < 16; r++) {
        const float* sp = s_sm + r * LP;
        #pragma unroll
        for (int nn = 0; nn < 8; nn++) {
            int n = nn * 8 + w;
            const float4* pv4 = (const float4*)(sp + n * 8);   // 32B aligned
            float4 f0 = pv4[0], f1 = pv4[1], f2 = pv4[2], f3 = pv4[3];
            float acc = bj;
            acc = fmaf(f0.x, wj[0], acc);
            acc = fmaf(f0.y, wj[1], acc);
            acc = fmaf(f0.z, wj[2], acc);
            acc = fmaf(f0.w, wj[3], acc);
            acc = fmaf(f1.x, wj[4], acc);
            acc = fmaf(f1.y, wj[5], acc);
            acc = fmaf(f1.z, wj[6], acc);
            acc = fmaf(f1.w, wj[7], acc);
            acc = fmaf(f2.x, wj[8], acc);
            acc = fmaf(f2.y, wj[9], acc);
            acc = fmaf(f2.z, wj[10], acc);
            acc = fmaf(f2.w, wj[11], acc);
            acc = fmaf(f3.x, wj[12], acc);
            acc = fmaf(f3.y, wj[13], acc);
            acc = fmaf(f3.z, wj[14], acc);
            acc = fmaf(f3.w, wj[15], acc);
            float g = geluf(acc);
            ps[nn] += g;
            pq[nn] = fmaf(g, g, pq[nn]);
            stage[lane * 65 + n] = g;
        }
        __syncthreads();
        float* dst = g_h + (bc0 + r) * 2048;
        for (int i = t; i < 2048; i += 256)
            dst[i] = stage[(i >> 6) * 65 + (i & 63)];
        __syncthreads();
    }
    #pragma unroll
    for (int nn = 0; nn < 8; nn++) {
        float s = ps[nn], q = pq[nn];
        #pragma unroll
        for (int off = 16; off; off >>= 1) {
            s += __shfl_down_sync(0xffffffff, s, off);
            q += __shfl_down_sync(0xffffffff, q, off);
        }
        if (lane == 0) {
            int n = nn * 8 + w;
            g_p1s[blockIdx.x * 64 + n] = s;
            g_p1q[blockIdx.x * 64 + n] = q;
        }
    }
}

// ---------------- K3/K5: reduce bn partials ----------------
__global__ void __launch_bounds__(1024) k3_stats1(const float* __restrict__ bn_w,
                                                  const float* __restrict__ bn_b) {
    __shared__ float ss[1024], qq[1024];
    int t = threadIdx.x;
    int n = t & 63, part = t >> 6;
    float s = 0.f, q = 0.f;
    for (int blk = part; blk < NB1; blk += 16) { s += g_p1s[blk * 64 + n]; q += g_p1q[blk * 64 + n]; }
    ss[t] = s; qq[t] = q;
    __syncthreads();
    if (t < 64) {
        float S = 0.f, Q = 0.f;
        #pragma unroll
        for (int i = 0; i < 16; i++) { S += ss[t + 64 * i]; Q += qq[t + 64 * i]; }
        float inv = 1.f / CNT_BN;
        float mu = S * inv;
        float var = fmaxf(Q * inv - mu * mu, 0.f);
        float sc = bn_w[t] * rsqrtf(var + EPS_);
        g_sc1[t] = sc;
        g_bi1[t] = fmaf(-mu, sc, bn_b[t]);
    }
}
__global__ void __launch_bounds__(1024) k5_stats2(const float* __restrict__ bn_w,
                                                  const float* __restrict__ bn_b) {
    __shared__ float ss[1024], qq[1024];
    int t = threadIdx.x;
    int n = t & 63, part = t >> 6;
    float s = 0.f, q = 0.f;
    for (int blk = part; blk < NB1; blk += 16) { s += g_p2s[blk * 64 + n]; q += g_p2q[blk * 64 + n]; }
    ss[t] = s; qq[t] = q;
    __syncthreads();
    if (t < 64) {
        float S = 0.f, Q = 0.f;
        #pragma unroll
        for (int i = 0; i < 16; i++) { S += ss[t + 64 * i]; Q += qq[t + 64 * i]; }
        float inv = 1.f / CNT_BN;
        float mu = S * inv;
        float var = fmaxf(Q * inv - mu * mu, 0.f);
        float sc = bn_w[t] * rsqrtf(var + EPS_);
        g_sc2[t] = sc;
        g_bi2[t] = fmaf(-mu, sc, bn_b[t]);
    }
}

// ---------------- K4: read g_h, bn1 affine + conv3 + gelu; bn2 partials ----------------
__global__ void __launch_bounds__(256) k4_conv(const float* __restrict__ conv_w,
                                               const float* __restrict__ conv_b) {
    __shared__ float rs[256], rq[256];
    int t = threadIdx.x;
    size_t bc0 = (size_t)blockIdx.x * 16;
    int n = t & 63;
    float sc = g_sc1[n], bi = g_bi1[n];
    float c0 = conv_w[n * 3], c1 = conv_w[n * 3 + 1], c2 = conv_w[n * 3 + 2];
    float cbv = conv_b[n];
    float psum = 0.f, psq = 0.f;
    #pragma unroll
    for (int q = 0; q < 4; q++) {
        int pair = t + 256 * q;
        int row = pair >> 6;
        const float* hp = g_h + (bc0 + row) * 2048 + n;
        float a[34];
        a[0] = 0.f; a[33] = 0.f;
        #pragma unroll
        for (int j = 0; j < 32; j++) a[j + 1] = fmaf(hp[j * 64], sc, bi);
        #pragma unroll
        for (int j = 0; j < 32; j++) {
            float vv = cbv;
            vv = fmaf(a[j], c0, vv);
            vv = fmaf(a[j + 1], c1, vv);
            vv = fmaf(a[j + 2], c2, vv);
            float g = geluf(vv);
            psum += g;
            psq = fmaf(g, g, psq);
        }
    }
    rs[t] = psum; rq[t] = psq;
    __syncthreads();
    if (t < 64) {
        float S = rs[t] + rs[t + 64] + rs[t + 128] + rs[t + 192];
        float Q = rq[t] + rq[t + 64] + rq[t + 128] + rq[t + 192];
        g_p2s[blockIdx.x * 64 + t] = S;
        g_p2q[blockIdx.x * 64 + t] = Q;
    }
}

// ---------------- Kg: gating MLP, warp-per-row, 32 rows/block ----------------
__global__ void __launch_bounds__(256) kg_gate(const float* __restrict__ m1_w,
                                               const float* __restrict__ m1_b,
                                               const float* __restrict__ m2_w,
                                               const float* __restrict__ m2_b) {
    extern __shared__ float kg_sm[];
    float* m1p = kg_sm;                 // 8320
    float* m2t = kg_sm + 8320;          // 8192
    float* ps  = kg_sm + 16512;         // 2048
    float* us  = kg_sm + 18560;         // 1024
    int t = threadIdx.x;
    int w = t >> 5, lane = t & 31;
    size_t bc0 = (size_t)blockIdx.x * 32;
    for (int i = t; i < 8192; i += 256) {
        int h = i >> 6, k = i & 63;
        m1p[h * 65 + k] = m1_w[i];
    }
    for (int i = t; i < 8192; i += 256) {
        int nn = i >> 7, h = i & 127;
        m2t[h * 64 + nn] = m2_w[i];
    }
    for (int i = t; i < 2048; i += 256)
        ps[i] = g_pool[bc0 * 64 + i];
    __syncthreads();
    float* uw = us + w * 128;
    #pragma unroll
    for (int rr = 0; rr < 4; rr++) {
        int rloc = rr * 8 + w;
        const float* pr = ps + rloc * 64;
        float u0 = m1_b[lane], u1 = m1_b[lane + 32], u2 = m1_b[lane + 64], u3 = m1_b[lane + 96];
        #pragma unroll 8
        for (int k = 0; k < 64; k++) {
            float pk = pr[k];
            u0 = fmaf(pk, m1p[lane * 65 + k], u0);
            u1 = fmaf(pk, m1p[(lane + 32) * 65 + k], u1);
            u2 = fmaf(pk, m1p[(lane + 64) * 65 + k], u2);
            u3 = fmaf(pk, m1p[(lane + 96) * 65 + k], u3);
        }
        uw[lane] = geluf(u0);
        uw[lane + 32] = geluf(u1);
        uw[lane + 64] = geluf(u2);
        uw[lane + 96] = geluf(u3);
        __syncwarp();
        float a0 = m2_b[lane], a1 = m2_b[lane + 32];
        #pragma unroll 8
        for (int h = 0; h < 128; h++) {
            float uh = uw[h];
            a0 = fmaf(uh, m2t[h * 64 + lane], a0);
            a1 = fmaf(uh, m2t[h * 64 + lane + 32], a1);
        }
        g_w[(bc0 + rloc) * 64 + lane] = sigf(a0);
        g_w[(bc0 + rloc) * 64 + lane + 32] = sigf(a1);
        __syncwarp();
    }
}

// ---------------- K6: read g_h, chain conv/bn2/fc2 + combine + LN -> g_y (staged stores) ----------------
__global__ void __launch_bounds__(256) k6_local(const float* __restrict__ conv_w,
                                                const float* __restrict__ conv_b,
                                                const float* __restrict__ fc2_w,
                                                const float* __restrict__ fc2_b,
                                                const float* __restrict__ gl_scale,
                                                const float* __restrict__ ln_w,
                                                const float* __restrict__ ln_b) {
    extern __shared__ float k6_sm[];
    float* s_sm = k6_sm;                       // 8320 floats
    float* w2 = k6_sm + 16 * LP;               // 512
    float* ystage = k6_sm + 16 * LP + 512;     // 4*1088 = 4352
    __shared__ float b2[16], lw[16], lb[16];
    int t = threadIdx.x;
    size_t bc0 = (size_t)blockIdx.x * 16;
    w2[t] = fc2_w[t];
    w2[t + 256] = fc2_w[t + 256];
    if (t < 16) { b2[t] = fc2_b[t]; lw[t] = ln_w[t]; lb[t] = ln_b[t]; }
    for (int i = t; i < 16 * LP; i += 256) s_sm[i] = g_s[bc0 * LP + i];
    __syncthreads();
    float gs = gl_scale[0];
    int n = t & 63;
    float sc1v = g_sc1[n], bi1v = g_bi1[n];
    float sc2v = g_sc2[n], bi2v = g_bi2[n];
    float c0 = conv_w[n * 3], c1 = conv_w[n * 3 + 1], c2 = conv_w[n * 3 + 2];
    float cbv = conv_b[n];
    #pragma unroll
    for (int q = 0; q < 4; q++) {
        int pair = t + 256 * q;
        int row = pair >> 6;
        int r4 = row & 3;
        size_t bc = bc0 + row;
        const float* hp = g_h + bc * 2048 + n;
        float a[34];
        a[0] = 0.f; a[33] = 0.f;
        #pragma unroll
        for (int j = 0; j < 32; j++) a[j + 1] = fmaf(hp[j * 64], sc1v, bi1v);
        float left = 0.f;
        #pragma unroll
        for (int j = 0; j < 32; j++) {
            float cur = a[j + 1];
            float vv = cbv;
            vv = fmaf(left, c0, vv);
            vv = fmaf(cur, c1, vv);
            vv = fmaf(a[j + 2], c2, vv);
            left = cur;
            a[j + 1] = fmaf(geluf(vv), sc2v, bi2v);
        }
        float p[16];
        const float4* spp = (const float4*)(s_sm + row * LP + n * 8);
        #pragma unroll
        for (int v = 0; v < 4; v++) {
            float4 f = spp[v];
            p[4 * v] = f.x; p[4 * v + 1] = f.y; p[4 * v + 2] = f.z; p[4 * v + 3] = f.w;
        }
        float wv = g_w[bc * 64 + n];
        float m3 = fmaf(gs, wv, 3.f);
        float y[16];
        float musum = 0.f;
        #pragma unroll
        for (int pp = 0; pp < 16; pp++) {
            float acc = b2[pp];
            const float4* wp = (const float4*)(w2 + pp * 32);
            #pragma unroll
            for (int j = 0; j < 8; j++) {
                float4 f = wp[j];
                acc = fmaf(a[4 * j + 1], f.x, acc);
                acc = fmaf(a[4 * j + 2], f.y, acc);
                acc = fmaf(a[4 * j + 3], f.z, acc);
                acc = fmaf(a[4 * j + 4], f.w, acc);
            }
            float yy = fmaf(p[pp], m3, acc);
            y[pp] = yy;
            musum += yy;
        }
        float mu = musum * (1.f / 16.f);
        float s2 = 0.f;
        #pragma unroll
        for (int pp = 0; pp < 16; pp++) { float d = y[pp] - mu; s2 = fmaf(d, d, s2); }
        float r = rsqrtf(s2 * (1.f / 16.f) + EPS_);
        float* yst = ystage + r4 * 1088 + n * 17;
        #pragma unroll
        for (int pp = 0; pp < 16; pp++)
            yst[pp] = fmaf((y[pp] - mu) * r, lw[pp], lb[pp]);
        __syncthreads();
        {
            float* gyb = g_y + (bc0 + (size_t)q * 4) * 1024;
            for (int i = t; i < 4096; i += 256) {
                int rr = i >> 10, k = i & 1023;
                gyb[rr * 1024 + k] = ystage[rr * 1088 + (k >> 4) * 17 + (k & 15)];
            }
        }
        __syncthreads();
    }
}

// ---------------- K7: fused final GEMM + un-RevIN + transpose ----------------
// 321 blocks; block tile 64 rows x 96 cols; 256 threads; thread tile 4x6
// As row-major [64][20]; a-LDS conflict-free (4-row ty spacing: 80 mod 32 = 16)
__global__ void __launch_bounds__(256) k7_gemm(const float* __restrict__ rev_w,
                                               const float* __restrict__ rev_b,
                                               float* __restrict__ out) {
    __shared__ float As[2][64 * 20];
    __shared__ float Bs[2][16 * 96];
    int t = threadIdx.x;
    size_t bc0 = (size_t)blockIdx.x * 64;
    int ty = t >> 4, tx = t & 15;                    // ty 0..15, tx 0..15
    int r0 = ty * 4, c0l = tx * 6;

    int lr = t >> 2, lk = (t & 3) * 4;               // As: 256 thr x 4 floats

    uint32_t as_sm[2], bs_sm[2];
    as_sm[0] = (uint32_t)__cvta_generic_to_shared(&As[0][0]);
    as_sm[1] = (uint32_t)__cvta_generic_to_shared(&As[1][0]);
    bs_sm[0] = (uint32_t)__cvta_generic_to_shared(&Bs[0][0]);
    bs_sm[1] = (uint32_t)__cvta_generic_to_shared(&Bs[1][0]);

    float acc[4][6];
    #pragma unroll
    for (int i = 0; i < 4; i++)
        #pragma unroll
        for (int j = 0; j < 6; j++) acc[i][j] = 0.f;

    auto load_tile = [&](int it, int bu) {
        int k0 = it * 16;
        const float* srcrow;
        if (k0 < 1024) srcrow = g_y + (bc0 + lr) * 1024 + k0 + lk;
        else           srcrow = g_trend + (bc0 + lr) * 512 + (k0 - 1024) + lk;
        cpa16(as_sm[bu] + (uint32_t)((lr * 20 + lk) * 4), srcrow);
        // Bs tile = 1536 contiguous floats of g_Wt
        if (t < 192) {
            int bi = t * 8;
            const float* bsrc = g_Wt + k0 * 96 + bi;
            uint32_t d = bs_sm[bu] + (uint32_t)(bi * 4);
            cpa16(d, bsrc);
            cpa16(d + 16, bsrc + 4);
        }
    };

    load_tile(0, 0);
    cp_commit();
    for (int it = 0; it < 96; it++) {
        int cur = it & 1;
        if (it + 1 < 96) {
            load_tile(it + 1, cur ^ 1);
            cp_commit();
            asm volatile("cp.async.wait_group 1;\n" ::: "memory");
        } else {
            asm volatile("cp.async.wait_group 0;\n" ::: "memory");
        }
        __syncthreads();
        #pragma unroll
        for (int k = 0; k < 16; k++) {
            float a4[4];
            #pragma unroll
            for (int i = 0; i < 4; i++) a4[i] = As[cur][(r0 + i) * 20 + k];
            const float* bp = &Bs[cur][k * 96 + c0l];
            float b6[6];
            #pragma unroll
            for (int j = 0; j < 6; j++) b6[j] = bp[j];
            #pragma unroll
            for (int i = 0; i < 4; i++)
                #pragma unroll
                for (int j = 0; j < 6; j++)
                    acc[i][j] = fmaf(a4[i], b6[j], acc[i][j]);
        }
        __syncthreads();
    }
    #pragma unroll
    for (int i = 0; i < 4; i++) {
        size_t bc = bc0 + r0 + i;
        int b = (int)(bc / C_);
        int c = (int)(bc - (size_t)b * C_);
        float rw = rev_w[c], rb = rev_b[c];
        float sd = g_std[bc], mn = g_mean[bc];
        #pragma unroll
        for (int j = 0; j < 6; j++) {
            int col = c0l + j;
            float v = acc[i][j] + g_cb[col];
            v = fmaf((v - rb) / rw, sd, mn);
            out[((size_t)b * PRED_ + col) * C_ + c] = v;
        }
    }
}

// ---------------- launch ----------------
extern "C" void kernel_launch(void* const* d_in, const int* in_sizes, int n_in,
                              void* d_out, int out_size) {
    const float* x       = (const float*)d_in[0];
    const float* rev_w   = (const float*)d_in[1];
    const float* rev_b   = (const float*)d_in[2];
    const float* fc1_w   = (const float*)d_in[3];
    const float* fc1_b   = (const float*)d_in[4];
    const float* bn1_w   = (const float*)d_in[5];
    const float* bn1_b   = (const float*)d_in[6];
    const float* conv_w  = (const float*)d_in[7];
    const float* conv_b  = (const float*)d_in[8];
    const float* bn2_w   = (const float*)d_in[9];
    const float* bn2_b   = (const float*)d_in[10];
    const float* fc2_w   = (const float*)d_in[11];
    const float* fc2_b   = (const float*)d_in[12];
    const float* m1_w    = (const float*)d_in[13];
    const float* m1_b    = (const float*)d_in[14];
    const float* m2_w    = (const float*)d_in[15];
    const float* m2_b    = (const float*)d_in[16];
    const float* gl_sc   = (const float*)d_in[17];
    const float* ln_w    = (const float*)d_in[18];
    const float* ln_b    = (const float*)d_in[19];
    const float* seas_w  = (const float*)d_in[20];
    const float* seas_b  = (const float*)d_in[21];
    const float* tr_w    = (const float*)d_in[22];
    const float* tr_b    = (const float*)d_in[23];
    const float* fus_w   = (const float*)d_in[24];
    const float* fus_b   = (const float*)d_in[25];
    float* out = (float*)d_out;

    const int K1_SMEM = 512 * 33 * 2 * sizeof(float);   // 135168
    const int KG_SMEM = 19584 * sizeof(float);           // 78336
    const int K6_SMEM = (16 * LP + 512 + 4 * 1088) * sizeof(float);
    cudaFuncSetAttribute(k1a_prep, cudaFuncAttributeMaxDynamicSharedMemorySize, K1_SMEM);
    cudaFuncSetAttribute(kg_gate, cudaFuncAttributeMaxDynamicSharedMemorySize, KG_SMEM);
    cudaFuncSetAttribute(k6_local, cudaFuncAttributeMaxDynamicSharedMemorySize, K6_SMEM);

    k1a_prep<<<dim3(11, 64), 256, K1_SMEM>>>(x, rev_w, rev_b);   // 1
    k0_fold1<<<384, 256>>>(seas_w, fus_w);                        // 2
    k0_fold2<<<192, 256>>>(tr_w, fus_w);                          // 3
    kg_gate<<<642, 256, KG_SMEM>>>(m1_w, m1_b, m2_w, m2_b);       // 4 -> profiled
    k1b_fc1<<<NB1, 256>>>(fc1_w, fc1_b);
    k3_stats1<<<1, 1024>>>(bn1_w, bn1_b);
    k4_conv<<<NB1, 256>>>(conv_w, conv_b);
    k5_stats2<<<1, 1024>>>(bn2_w, bn2_b);
    k6_local<<<NB1, 256, K6_SMEM>>>(conv_w, conv_b, fc2_w, fc2_b, gl_sc, ln_w, ln_b);
    k0_cb<<<1, 96>>>(fus_w, fus_b, seas_b, tr_b);
    k7_gemm<<<321, 256>>>(rev_w, rev_b, out);
    (void)in_sizes; (void)n_in; (void)out_size;
}

// round 13
// speedup vs baseline: 1.0544x; 1.0544x over previous
#include <cuda_runtime.h>
#include <cuda_bf16.h>
#include <math.h>
#include <stdint.h>
#include <stddef.h>

#define B_ 64
#define L_ 512
#define C_ 321
#define BC 20544            // B_*C_
#define PRED_ 96
#define LP 520              // L + STRIDE
#define NB1 1284            // BC/16 blocks (k1b/k4/k6)
#define CNT_BN 657408.0f    // BC*32
#define EPS_ 1e-5f

// ---------------- scratch (__device__ globals; no runtime allocation) ----------------
static __device__ float g_s[(size_t)BC * LP];        // seasonal, padded
static __device__ float g_trend[(size_t)BC * L_];    // trend rows [bc][L]
static __device__ float g_mean[BC];
static __device__ float g_std[BC];
static __device__ float g_h[(size_t)BC * 2048];      // h1 = gelu(fc1), layout [bc][j(32)][n(64)]
static __device__ float g_y[(size_t)BC * 1024];      // post-LN y [bc][1024]
static __device__ float g_pool[(size_t)BC * 64];     // sp.mean(-1)
static __device__ float g_w[(size_t)BC * 64];        // gating sigmoid output
static __device__ float g_Wt[1536 * 96];             // folded weights, [k][j]
static __device__ float g_cb[96];                    // folded bias
static __device__ float g_p1s[NB1 * 64];
static __device__ float g_p1q[NB1 * 64];
static __device__ float g_p2s[NB1 * 64];
static __device__ float g_p2q[NB1 * 64];
static __device__ float g_sc1[64], g_bi1[64], g_sc2[64], g_bi2[64];

__device__ __forceinline__ float geluf(float v) {
    return 0.5f * v * (1.0f + erff(v * 0.70710678f));
}
__device__ __forceinline__ float sigf(float v) {
    return 1.0f / (1.0f + expf(-v));
}

// cp.async helpers (LDGSTS)
__device__ __forceinline__ void cpa16(uint32_t d, const float* s) {
    asm volatile("cp.async.ca.shared.global [%0], [%1], 16;\n" :: "r"(d), "l"(s));
}
__device__ __forceinline__ void cp_commit() {
    asm volatile("cp.async.commit_group;\n" ::: "memory");
}

// ---------------- K0: fold fusion layer ----------------
__global__ void k0_fold1(const float* __restrict__ seas_w, const float* __restrict__ fus_w) {
    int idx = blockIdx.x * 256 + threadIdx.x;       // 96*1024
    int j = idx >> 10, m = idx & 1023;
    const float* fw = fus_w + j * 192;
    float a = 0.f;
    #pragma unroll 8
    for (int k = 0; k < 96; k++) a = fmaf(fw[k], seas_w[k * 1024 + m], a);
    g_Wt[m * 96 + j] = a;
}
__global__ void k0_fold2(const float* __restrict__ tr_w, const float* __restrict__ fus_w) {
    int idx = blockIdx.x * 256 + threadIdx.x;       // 96*512
    int j = idx >> 9, m = idx & 511;
    const float* fw = fus_w + j * 192 + 96;
    float a = 0.f;
    #pragma unroll 8
    for (int k = 0; k < 96; k++) a = fmaf(fw[k], tr_w[k * 512 + m], a);
    g_Wt[(1024 + m) * 96 + j] = a;
}
__global__ void k0_cb(const float* __restrict__ fus_w, const float* __restrict__ fus_b,
                      const float* __restrict__ seas_b, const float* __restrict__ tr_b) {
    int j = threadIdx.x;
    float a = fus_b[j];
    for (int k = 0; k < 96; k++) {
        a = fmaf(fus_w[j * 192 + k], seas_b[k], a);
        a = fmaf(fus_w[j * 192 + 96 + k], tr_b[k], a);
    }
    g_cb[j] = a;
}

// ---------------- K1a: RevIN stats + segmented EMA + seasonal/trend + pooled ----------------
__global__ void __launch_bounds__(256) k1a_prep(const float* __restrict__ x,
                                                const float* __restrict__ rev_w,
                                                const float* __restrict__ rev_b) {
    extern __shared__ float sm[];
    float* xb = sm;                 // [512][33]
    float* tb = sm + 512 * 33;      // [512][33]
    __shared__ float red_s[8][33], red_q[8][33], meanb[32], stdb[32];
    __shared__ float segend[8][33], carry[8][33];
    __shared__ float pw[65];
    int b = blockIdx.y;
    int c0 = blockIdx.x * 32;
    int t = threadIdx.x;
    int w = t >> 5, lane = t & 31;
    int c = c0 + lane;
    bool cv = (c < C_);

    if (t == 0) {
        pw[0] = 1.f;
        for (int j = 1; j <= 64; j++) pw[j] = pw[j - 1] * 0.8f;
    }

    float s = 0.f, q = 0.f;
    for (int l = w; l < L_; l += 8) {
        float v = cv ? x[((size_t)b * L_ + l) * C_ + c] : 0.f;
        xb[l * 33 + lane] = v;
        s += v;
        q = fmaf(v, v, q);
    }
    red_s[w][lane] = s; red_q[w][lane] = q;
    __syncthreads();
    if (w == 0) {
        float ss = 0.f, qq = 0.f;
        #pragma unroll
        for (int i = 0; i < 8; i++) { ss += red_s[i][lane]; qq += red_q[i][lane]; }
        float mu = ss * (1.f / (float)L_);
        float v2 = fmaxf(qq - (float)L_ * mu * mu, 0.f);
        float sd = sqrtf(v2 * (1.f / (float)(L_ - 1))) + EPS_;
        meanb[lane] = mu; stdb[lane] = sd;
        if (cv) { int bc = b * C_ + c; g_mean[bc] = mu; g_std[bc] = sd; }
    }
    __syncthreads();
    {
        float rw = cv ? rev_w[c] : 1.f;
        float rb = cv ? rev_b[c] : 0.f;
        float mu = meanb[lane], inv = 1.f / stdb[lane];
        for (int l = w; l < L_; l += 8) {
            float v = xb[l * 33 + lane];
            xb[l * 33 + lane] = fmaf((v - mu) * inv, rw, rb);
        }
    }
    __syncthreads();
    {
        int base = w * 64;
        float cl;
        if (w == 0) {
            cl = xb[lane];
            tb[lane] = cl;
            #pragma unroll 4
            for (int l = 1; l < 64; l++) {
                cl = fmaf(0.8f, cl, 0.2f * xb[l * 33 + lane]);
                tb[l * 33 + lane] = cl;
            }
        } else {
            cl = 0.f;
            #pragma unroll 4
            for (int j = 0; j < 64; j++) {
                int l = base + j;
                cl = fmaf(0.8f, cl, 0.2f * xb[l * 33 + lane]);
                tb[l * 33 + lane] = cl;
            }
        }
        segend[w][lane] = cl;
    }
    __syncthreads();
    if (t < 32) {
        float cacc = segend[0][t];
        carry[1][t] = cacc;
        float q64 = pw[64];
        #pragma unroll
        for (int s2 = 1; s2 <= 6; s2++) {
            cacc = fmaf(q64, cacc, segend[s2][t]);
            carry[s2 + 1][t] = cacc;
        }
    }
    __syncthreads();
    {
        int base = w * 64;
        float cin = (w == 0) ? 0.f : carry[w][lane];
        #pragma unroll 4
        for (int j = 0; j < 64; j++) {
            int l = base + j;
            float tf = fmaf(pw[j + 1], cin, tb[l * 33 + lane]);
            tb[l * 33 + lane] = tf;
            xb[l * 33 + lane] = xb[l * 33 + lane] - tf;
        }
    }
    __syncthreads();
    for (int ci = w; ci < 32; ci += 8) {
        int cc = c0 + ci;
        if (cc >= C_) continue;
        size_t bc = (size_t)b * C_ + cc;
        float* gs = g_s + bc * LP;
        float* gt = g_trend + bc * (size_t)L_;
        for (int l0 = 0; l0 < L_; l0 += 32) {
            gs[l0 + lane] = xb[(l0 + lane) * 33 + ci];
            gt[l0 + lane] = tb[(l0 + lane) * 33 + ci];
        }
        if (lane < 8) gs[L_ + lane] = xb[511 * 33 + ci];
        #pragma unroll
        for (int nn = 0; nn < 2; nn++) {
            int n = 2 * lane + nn;
            float sum = 0.f;
            #pragma unroll
            for (int p = 0; p < 16; p++) {
                int l = n * 8 + p;
                if (l > 511) l = 511;
                sum += xb[l * 33 + ci];
            }
            g_pool[bc * 64 + n] = sum * (1.f / 16.f);
        }
    }
}

// ---------------- K1b: fc1 + gelu -> g_h ([bc][j][n]); bn1 per-n partials ----------------
__global__ void __launch_bounds__(256) k1b_fc1(const float* __restrict__ fc1_w,
                                               const float* __restrict__ fc1_b) {
    __shared__ float s_sm[16 * LP];       // 33280B
    __shared__ float wt[512];             // wt[p*32+j] = fc1_w[j*16+p]
    __shared__ float stage[32 * 65];      // [j][n] padded
    int t = threadIdx.x;
    int w = t >> 5, lane = t & 31;
    size_t bc0 = (size_t)blockIdx.x * 16;
    for (int i = t; i < 512; i += 256) {
        int p = i >> 5, j = i & 31;
        wt[i] = fc1_w[j * 16 + p];
    }
    for (int i = t; i < 16 * LP; i += 256) s_sm[i] = g_s[bc0 * LP + i];
    __syncthreads();
    float wj[16];
    #pragma unroll
    for (int p = 0; p < 16; p++) wj[p] = wt[p * 32 + lane];
    float bj = fc1_b[lane];
    float ps[8], pq[8];
    #pragma unroll
    for (int i = 0; i < 8; i++) { ps[i] = 0.f; pq[i] = 0.f; }

    for (int r = 0; r < 16; r++) {
        const float* sp = s_sm + r * LP;
        #pragma unroll
        for (int nn = 0; nn < 8; nn++) {
            int n = nn * 8 + w;
            const float4* pv4 = (const float4*)(sp + n * 8);
            float4 f0 = pv4[0], f1 = pv4[1], f2 = pv4[2], f3 = pv4[3];
            float acc = bj;
            acc = fmaf(f0.x, wj[0], acc);
            acc = fmaf(f0.y, wj[1], acc);
            acc = fmaf(f0.z, wj[2], acc);
            acc = fmaf(f0.w, wj[3], acc);
            acc = fmaf(f1.x, wj[4], acc);
            acc = fmaf(f1.y, wj[5], acc);
            acc = fmaf(f1.z, wj[6], acc);
            acc = fmaf(f1.w, wj[7], acc);
            acc = fmaf(f2.x, wj[8], acc);
            acc = fmaf(f2.y, wj[9], acc);
            acc = fmaf(f2.z, wj[10], acc);
            acc = fmaf(f2.w, wj[11], acc);
            acc = fmaf(f3.x, wj[12], acc);
            acc = fmaf(f3.y, wj[13], acc);
            acc = fmaf(f3.z, wj[14], acc);
            acc = fmaf(f3.w, wj[15], acc);
            float g = geluf(acc);
            ps[nn] += g;
            pq[nn] = fmaf(g, g, pq[nn]);
            stage[lane * 65 + n] = g;
        }
        __syncthreads();
        float* dst = g_h + (bc0 + r) * 2048;
        for (int i = t; i < 2048; i += 256)
            dst[i] = stage[(i >> 6) * 65 + (i & 63)];
        __syncthreads();
    }
    #pragma unroll
    for (int nn = 0; nn < 8; nn++) {
        float s = ps[nn], q = pq[nn];
        #pragma unroll
        for (int off = 16; off; off >>= 1) {
            s += __shfl_down_sync(0xffffffff, s, off);
            q += __shfl_down_sync(0xffffffff, q, off);
        }
        if (lane == 0) {
            int n = nn * 8 + w;
            g_p1s[blockIdx.x * 64 + n] = s;
            g_p1q[blockIdx.x * 64 + n] = q;
        }
    }
}

// ---------------- K3/K5: reduce bn partials ----------------
__global__ void __launch_bounds__(1024) k3_stats1(const float* __restrict__ bn_w,
                                                  const float* __restrict__ bn_b) {
    __shared__ float ss[1024], qq[1024];
    int t = threadIdx.x;
    int n = t & 63, part = t >> 6;
    float s = 0.f, q = 0.f;
    for (int blk = part; blk < NB1; blk += 16) { s += g_p1s[blk * 64 + n]; q += g_p1q[blk * 64 + n]; }
    ss[t] = s; qq[t] = q;
    __syncthreads();
    if (t < 64) {
        float S = 0.f, Q = 0.f;
        #pragma unroll
        for (int i = 0; i < 16; i++) { S += ss[t + 64 * i]; Q += qq[t + 64 * i]; }
        float inv = 1.f / CNT_BN;
        float mu = S * inv;
        float var = fmaxf(Q * inv - mu * mu, 0.f);
        float sc = bn_w[t] * rsqrtf(var + EPS_);
        g_sc1[t] = sc;
        g_bi1[t] = fmaf(-mu, sc, bn_b[t]);
    }
}
__global__ void __launch_bounds__(1024) k5_stats2(const float* __restrict__ bn_w,
                                                  const float* __restrict__ bn_b) {
    __shared__ float ss[1024], qq[1024];
    int t = threadIdx.x;
    int n = t & 63, part = t >> 6;
    float s = 0.f, q = 0.f;
    for (int blk = part; blk < NB1; blk += 16) { s += g_p2s[blk * 64 + n]; q += g_p2q[blk * 64 + n]; }
    ss[t] = s; qq[t] = q;
    __syncthreads();
    if (t < 64) {
        float S = 0.f, Q = 0.f;
        #pragma unroll
        for (int i = 0; i < 16; i++) { S += ss[t + 64 * i]; Q += qq[t + 64 * i]; }
        float inv = 1.f / CNT_BN;
        float mu = S * inv;
        float var = fmaxf(Q * inv - mu * mu, 0.f);
        float sc = bn_w[t] * rsqrtf(var + EPS_);
        g_sc2[t] = sc;
        g_bi2[t] = fmaf(-mu, sc, bn_b[t]);
    }
}

// ---------------- K4: read g_h, bn1 affine + conv3 + gelu; bn2 partials ----------------
__global__ void __launch_bounds__(256) k4_conv(const float* __restrict__ conv_w,
                                               const float* __restrict__ conv_b) {
    __shared__ float rs[256], rq[256];
    int t = threadIdx.x;
    size_t bc0 = (size_t)blockIdx.x * 16;
    int n = t & 63;
    float sc = g_sc1[n], bi = g_bi1[n];
    float c0 = conv_w[n * 3], c1 = conv_w[n * 3 + 1], c2 = conv_w[n * 3 + 2];
    float cbv = conv_b[n];
    float psum = 0.f, psq = 0.f;
    #pragma unroll
    for (int q = 0; q < 4; q++) {
        int pair = t + 256 * q;
        int row = pair >> 6;
        const float* hp = g_h + (bc0 + row) * 2048 + n;
        float a[34];
        a[0] = 0.f; a[33] = 0.f;
        #pragma unroll
        for (int j = 0; j < 32; j++) a[j + 1] = fmaf(hp[j * 64], sc, bi);
        #pragma unroll
        for (int j = 0; j < 32; j++) {
            float vv = cbv;
            vv = fmaf(a[j], c0, vv);
            vv = fmaf(a[j + 1], c1, vv);
            vv = fmaf(a[j + 2], c2, vv);
            float g = geluf(vv);
            psum += g;
            psq = fmaf(g, g, psq);
        }
    }
    rs[t] = psum; rq[t] = psq;
    __syncthreads();
    if (t < 64) {
        float S = rs[t] + rs[t + 64] + rs[t + 128] + rs[t + 192];
        float Q = rq[t] + rq[t + 64] + rq[t + 128] + rq[t + 192];
        g_p2s[blockIdx.x * 64 + t] = S;
        g_p2q[blockIdx.x * 64 + t] = Q;
    }
}

// ---------------- Kg: gating MLP, 4 rows/warp batched (weight-LDS reuse) ----------------
// dynamic smem: m1p [128][65] | m2t [128][64] | ps [32][64] | us [32][128]
__global__ void __launch_bounds__(256) kg_gate(const float* __restrict__ m1_w,
                                               const float* __restrict__ m1_b,
                                               const float* __restrict__ m2_w,
                                               const float* __restrict__ m2_b) {
    extern __shared__ float kg_sm[];
    float* m1p = kg_sm;                 // 8320
    float* m2t = kg_sm + 8320;          // 8192
    float* ps  = kg_sm + 16512;         // 2048
    float* us  = kg_sm + 18560;         // 4096
    int t = threadIdx.x;
    int w = t >> 5, lane = t & 31;
    size_t bc0 = (size_t)blockIdx.x * 32;
    for (int i = t; i < 8192; i += 256) {
        int h = i >> 6, k = i & 63;
        m1p[h * 65 + k] = m1_w[i];
    }
    for (int i = t; i < 8192; i += 256) {
        int nn = i >> 7, h = i & 127;
        m2t[h * 64 + nn] = m2_w[i];
    }
    for (int i = t; i < 2048; i += 256)
        ps[i] = g_pool[bc0 * 64 + i];
    __syncthreads();
    int r0 = w * 4;
    // m1 phase: u[4 rows][4 h-chunks], weights loaded once per (k, chunk)
    float u[4][4];
    {
        float b0 = m1_b[lane], b1 = m1_b[lane + 32], b2 = m1_b[lane + 64], b3 = m1_b[lane + 96];
        #pragma unroll
        for (int r = 0; r < 4; r++) { u[r][0] = b0; u[r][1] = b1; u[r][2] = b2; u[r][3] = b3; }
    }
    #pragma unroll 4
    for (int k = 0; k < 64; k++) {
        float wv0 = m1p[lane * 65 + k];
        float wv1 = m1p[(lane + 32) * 65 + k];
        float wv2 = m1p[(lane + 64) * 65 + k];
        float wv3 = m1p[(lane + 96) * 65 + k];
        #pragma unroll
        for (int r = 0; r < 4; r++) {
            float pk = ps[(r0 + r) * 64 + k];        // lane-uniform broadcast
            u[r][0] = fmaf(pk, wv0, u[r][0]);
            u[r][1] = fmaf(pk, wv1, u[r][1]);
            u[r][2] = fmaf(pk, wv2, u[r][2]);
            u[r][3] = fmaf(pk, wv3, u[r][3]);
        }
    }
    #pragma unroll
    for (int r = 0; r < 4; r++) {
        float* uwr = us + (r0 + r) * 128;
        uwr[lane] = geluf(u[r][0]);
        uwr[lane + 32] = geluf(u[r][1]);
        uwr[lane + 64] = geluf(u[r][2]);
        uwr[lane + 96] = geluf(u[r][3]);
    }
    __syncwarp();
    // m2 phase: acc[4 rows][2 n-chunks]
    float acc[4][2];
    {
        float b0 = m2_b[lane], b1 = m2_b[lane + 32];
        #pragma unroll
        for (int r = 0; r < 4; r++) { acc[r][0] = b0; acc[r][1] = b1; }
    }
    #pragma unroll 4
    for (int h = 0; h < 128; h++) {
        float w0 = m2t[h * 64 + lane];
        float w1 = m2t[h * 64 + lane + 32];
        #pragma unroll
        for (int r = 0; r < 4; r++) {
            float uh = us[(r0 + r) * 128 + h];       // lane-uniform broadcast
            acc[r][0] = fmaf(uh, w0, acc[r][0]);
            acc[r][1] = fmaf(uh, w1, acc[r][1]);
        }
    }
    #pragma unroll
    for (int r = 0; r < 4; r++) {
        g_w[(bc0 + r0 + r) * 64 + lane] = sigf(acc[r][0]);
        g_w[(bc0 + r0 + r) * 64 + lane + 32] = sigf(acc[r][1]);
    }
}

// ---------------- K6: read g_h, chain conv/bn2/fc2 + combine + LN -> g_y (staged stores) ----------------
__global__ void __launch_bounds__(256) k6_local(const float* __restrict__ conv_w,
                                                const float* __restrict__ conv_b,
                                                const float* __restrict__ fc2_w,
                                                const float* __restrict__ fc2_b,
                                                const float* __restrict__ gl_scale,
                                                const float* __restrict__ ln_w,
                                                const float* __restrict__ ln_b) {
    extern __shared__ float k6_sm[];
    float* s_sm = k6_sm;                       // 8320 floats
    float* w2 = k6_sm + 16 * LP;               // 512
    float* ystage = k6_sm + 16 * LP + 512;     // 4*1088 = 4352
    __shared__ float b2[16], lw[16], lb[16];
    int t = threadIdx.x;
    size_t bc0 = (size_t)blockIdx.x * 16;
    w2[t] = fc2_w[t];
    w2[t + 256] = fc2_w[t + 256];
    if (t < 16) { b2[t] = fc2_b[t]; lw[t] = ln_w[t]; lb[t] = ln_b[t]; }
    for (int i = t; i < 16 * LP; i += 256) s_sm[i] = g_s[bc0 * LP + i];
    __syncthreads();
    float gs = gl_scale[0];
    int n = t & 63;
    float sc1v = g_sc1[n], bi1v = g_bi1[n];
    float sc2v = g_sc2[n], bi2v = g_bi2[n];
    float c0 = conv_w[n * 3], c1 = conv_w[n * 3 + 1], c2 = conv_w[n * 3 + 2];
    float cbv = conv_b[n];
    #pragma unroll
    for (int q = 0; q < 4; q++) {
        int pair = t + 256 * q;
        int row = pair >> 6;
        int r4 = row & 3;
        size_t bc = bc0 + row;
        const float* hp = g_h + bc * 2048 + n;
        float a[34];
        a[0] = 0.f; a[33] = 0.f;
        #pragma unroll
        for (int j = 0; j < 32; j++) a[j + 1] = fmaf(hp[j * 64], sc1v, bi1v);
        float left = 0.f;
        #pragma unroll
        for (int j = 0; j < 32; j++) {
            float cur = a[j + 1];
            float vv = cbv;
            vv = fmaf(left, c0, vv);
            vv = fmaf(cur, c1, vv);
            vv = fmaf(a[j + 2], c2, vv);
            left = cur;
            a[j + 1] = fmaf(geluf(vv), sc2v, bi2v);
        }
        float p[16];
        const float4* spp = (const float4*)(s_sm + row * LP + n * 8);
        #pragma unroll
        for (int v = 0; v < 4; v++) {
            float4 f = spp[v];
            p[4 * v] = f.x; p[4 * v + 1] = f.y; p[4 * v + 2] = f.z; p[4 * v + 3] = f.w;
        }
        float wv = g_w[bc * 64 + n];
        float m3 = fmaf(gs, wv, 3.f);
        float y[16];
        float musum = 0.f;
        #pragma unroll
        for (int pp = 0; pp < 16; pp++) {
            float acc = b2[pp];
            const float4* wp = (const float4*)(w2 + pp * 32);
            #pragma unroll
            for (int j = 0; j < 8; j++) {
                float4 f = wp[j];
                acc = fmaf(a[4 * j + 1], f.x, acc);
                acc = fmaf(a[4 * j + 2], f.y, acc);
                acc = fmaf(a[4 * j + 3], f.z, acc);
                acc = fmaf(a[4 * j + 4], f.w, acc);
            }
            float yy = fmaf(p[pp], m3, acc);
            y[pp] = yy;
            musum += yy;
        }
        float mu = musum * (1.f / 16.f);
        float s2 = 0.f;
        #pragma unroll
        for (int pp = 0; pp < 16; pp++) { float d = y[pp] - mu; s2 = fmaf(d, d, s2); }
        float r = rsqrtf(s2 * (1.f / 16.f) + EPS_);
        float* yst = ystage + r4 * 1088 + n * 17;
        #pragma unroll
        for (int pp = 0; pp < 16; pp++)
            yst[pp] = fmaf((y[pp] - mu) * r, lw[pp], lb[pp]);
        __syncthreads();
        {
            float* gyb = g_y + (bc0 + (size_t)q * 4) * 1024;
            for (int i = t; i < 4096; i += 256) {
                int rr = i >> 10, k = i & 1023;
                gyb[rr * 1024 + k] = ystage[rr * 1088 + (k >> 4) * 17 + (k & 15)];
            }
        }
        __syncthreads();
    }
}

// ---------------- K7: fused final GEMM + un-RevIN + transpose (R11 config) ----------------
// 321 blocks; block tile 64 rows x 96 cols; 128 threads; thread tile 8x6
__global__ void __launch_bounds__(128) k7_gemm(const float* __restrict__ rev_w,
                                               const float* __restrict__ rev_b,
                                               float* __restrict__ out) {
    __shared__ float As[2][64 * 20];
    __shared__ float Bs[2][16 * 96];
    int t = threadIdx.x;
    size_t bc0 = (size_t)blockIdx.x * 64;
    int ty = t >> 4, tx = t & 15;
    int r0 = ty * 8, c0l = tx * 6;

    int lr = t >> 1, lk = (t & 1) * 8;               // As: row lr (0..63), 8 contiguous k
    int bk = t >> 3, bo = (t & 7) * 12;              // Bs: k-row bk (0..15), 12 floats

    uint32_t as_sm[2], bs_sm[2];
    as_sm[0] = (uint32_t)__cvta_generic_to_shared(&As[0][0]);
    as_sm[1] = (uint32_t)__cvta_generic_to_shared(&As[1][0]);
    bs_sm[0] = (uint32_t)__cvta_generic_to_shared(&Bs[0][0]);
    bs_sm[1] = (uint32_t)__cvta_generic_to_shared(&Bs[1][0]);

    float acc[8][6];
    #pragma unroll
    for (int i = 0; i < 8; i++)
        #pragma unroll
        for (int j = 0; j < 6; j++) acc[i][j] = 0.f;

    auto load_tile = [&](int it, int bu) {
        int k0 = it * 16;
        const float* srcrow;
        if (k0 < 1024) srcrow = g_y + (bc0 + lr) * 1024 + k0 + lk;
        else           srcrow = g_trend + (bc0 + lr) * 512 + (k0 - 1024) + lk;
        uint32_t d = as_sm[bu] + (uint32_t)((lr * 20 + lk) * 4);
        cpa16(d, srcrow);
        cpa16(d + 16, srcrow + 4);
        const float* bsrc = g_Wt + (k0 + bk) * 96 + bo;
        #pragma unroll
        for (int i = 0; i < 3; i++)
            cpa16(bs_sm[bu] + (uint32_t)((bk * 96 + bo + 4 * i) * 4), bsrc + 4 * i);
    };

    load_tile(0, 0);
    cp_commit();
    for (int it = 0; it < 96; it++) {
        int cur = it & 1;
        if (it + 1 < 96) {
            load_tile(it + 1, cur ^ 1);
            cp_commit();
            asm volatile("cp.async.wait_group 1;\n" ::: "memory");
        } else {
            asm volatile("cp.async.wait_group 0;\n" ::: "memory");
        }
        __syncthreads();
        #pragma unroll
        for (int k = 0; k < 16; k++) {
            float a8[8];
            #pragma unroll
            for (int i = 0; i < 8; i++) a8[i] = As[cur][(r0 + i) * 20 + k];
            const float* bp = &Bs[cur][k * 96 + c0l];
            float b6[6];
            #pragma unroll
            for (int j = 0; j < 6; j++) b6[j] = bp[j];
            #pragma unroll
            for (int i = 0; i < 8; i++)
                #pragma unroll
                for (int j = 0; j < 6; j++)
                    acc[i][j] = fmaf(a8[i], b6[j], acc[i][j]);
        }
        __syncthreads();
    }
    #pragma unroll
    for (int i = 0; i < 8; i++) {
        size_t bc = bc0 + r0 + i;
        int b = (int)(bc / C_);
        int c = (int)(bc - (size_t)b * C_);
        float rw = rev_w[c], rb = rev_b[c];
        float sd = g_std[bc], mn = g_mean[bc];
        #pragma unroll
        for (int j = 0; j < 6; j++) {
            int col = c0l + j;
            float v = acc[i][j] + g_cb[col];
            v = fmaf((v - rb) / rw, sd, mn);
            out[((size_t)b * PRED_ + col) * C_ + c] = v;
        }
    }
}

// ---------------- launch ----------------
extern "C" void kernel_launch(void* const* d_in, const int* in_sizes, int n_in,
                              void* d_out, int out_size) {
    const float* x       = (const float*)d_in[0];
    const float* rev_w   = (const float*)d_in[1];
    const float* rev_b   = (const float*)d_in[2];
    const float* fc1_w   = (const float*)d_in[3];
    const float* fc1_b   = (const float*)d_in[4];
    const float* bn1_w   = (const float*)d_in[5];
    const float* bn1_b   = (const float*)d_in[6];
    const float* conv_w  = (const float*)d_in[7];
    const float* conv_b  = (const float*)d_in[8];
    const float* bn2_w   = (const float*)d_in[9];
    const float* bn2_b   = (const float*)d_in[10];
    const float* fc2_w   = (const float*)d_in[11];
    const float* fc2_b   = (const float*)d_in[12];
    const float* m1_w    = (const float*)d_in[13];
    const float* m1_b    = (const float*)d_in[14];
    const float* m2_w    = (const float*)d_in[15];
    const float* m2_b    = (const float*)d_in[16];
    const float* gl_sc   = (const float*)d_in[17];
    const float* ln_w    = (const float*)d_in[18];
    const float* ln_b    = (const float*)d_in[19];
    const float* seas_w  = (const float*)d_in[20];
    const float* seas_b  = (const float*)d_in[21];
    const float* tr_w    = (const float*)d_in[22];
    const float* tr_b    = (const float*)d_in[23];
    const float* fus_w   = (const float*)d_in[24];
    const float* fus_b   = (const float*)d_in[25];
    float* out = (float*)d_out;

    const int K1_SMEM = 512 * 33 * 2 * sizeof(float);   // 135168
    const int KG_SMEM = 22656 * sizeof(float);           // 90624
    const int K6_SMEM = (16 * LP + 512 + 4 * 1088) * sizeof(float);
    cudaFuncSetAttribute(k1a_prep, cudaFuncAttributeMaxDynamicSharedMemorySize, K1_SMEM);
    cudaFuncSetAttribute(kg_gate, cudaFuncAttributeMaxDynamicSharedMemorySize, KG_SMEM);
    cudaFuncSetAttribute(k6_local, cudaFuncAttributeMaxDynamicSharedMemorySize, K6_SMEM);

    k0_fold1<<<384, 256>>>(seas_w, fus_w);                        // 1
    k0_fold2<<<192, 256>>>(tr_w, fus_w);                          // 2
    k0_cb<<<1, 96>>>(fus_w, fus_b, seas_b, tr_b);                 // 3
    k1a_prep<<<dim3(11, 64), 256, K1_SMEM>>>(x, rev_w, rev_b);   // 4 -> profiled
    k1b_fc1<<<NB1, 256>>>(fc1_w, fc1_b);
    k3_stats1<<<1, 1024>>>(bn1_w, bn1_b);
    k4_conv<<<NB1, 256>>>(conv_w, conv_b);
    k5_stats2<<<1, 1024>>>(bn2_w, bn2_b);
    kg_gate<<<642, 256, KG_SMEM>>>(m1_w, m1_b, m2_w, m2_b);
    k6_local<<<NB1, 256, K6_SMEM>>>(conv_w, conv_b, fc2_w, fc2_b, gl_sc, ln_w, ln_b);
    k7_gemm<<<321, 128>>>(rev_w, rev_b, out);
    (void)in_sizes; (void)n_in; (void)out_size;
}

// round 14
// speedup vs baseline: 1.0959x; 1.0393x over previous
#include <cuda_runtime.h>
#include <cuda_bf16.h>
#include <math.h>
#include <stdint.h>
#include <stddef.h>

#define B_ 64
#define L_ 512
#define C_ 321
#define BC 20544            // B_*C_
#define PRED_ 96
#define LP 520              // L + STRIDE
#define NB1 1284            // BC/16 blocks (k1b/k4/k6)
#define CNT_BN 657408.0f    // BC*32
#define EPS_ 1e-5f

// ---------------- scratch (__device__ globals; no runtime allocation) ----------------
static __device__ float g_s[(size_t)BC * LP];        // seasonal, padded
static __device__ float g_trend[(size_t)BC * L_];    // trend rows [bc][L]
static __device__ float g_mean[BC];
static __device__ float g_std[BC];
static __device__ float g_h[(size_t)BC * 2048];      // h1 = gelu(fc1), layout [bc][j(32)][n(64)]
static __device__ float g_y[(size_t)BC * 1024];      // post-LN y [bc][1024]
static __device__ float g_pool[(size_t)BC * 64];     // sp.mean(-1)
static __device__ float g_w[(size_t)BC * 64];        // gating sigmoid output
static __device__ float g_Wt[1536 * 96];             // folded weights, [k][j]
static __device__ float g_cb[96];                    // folded bias
static __device__ float g_p1s[NB1 * 64];
static __device__ float g_p1q[NB1 * 64];
static __device__ float g_p2s[NB1 * 64];
static __device__ float g_p2q[NB1 * 64];
static __device__ float g_sc1[64], g_bi1[64], g_sc2[64], g_bi2[64];

__device__ __forceinline__ float geluf(float v) {
    return 0.5f * v * (1.0f + erff(v * 0.70710678f));
}
__device__ __forceinline__ float sigf(float v) {
    return 1.0f / (1.0f + expf(-v));
}

// cp.async helpers (LDGSTS)
__device__ __forceinline__ void cpa16(uint32_t d, const float* s) {
    asm volatile("cp.async.ca.shared.global [%0], [%1], 16;\n" :: "r"(d), "l"(s));
}
__device__ __forceinline__ void cp_commit() {
    asm volatile("cp.async.commit_group;\n" ::: "memory");
}

// ---------------- K0: fold fusion layer ----------------
__global__ void k0_fold1(const float* __restrict__ seas_w, const float* __restrict__ fus_w) {
    int idx = blockIdx.x * 256 + threadIdx.x;       // 96*1024
    int j = idx >> 10, m = idx & 1023;
    const float* fw = fus_w + j * 192;
    float a = 0.f;
    #pragma unroll 8
    for (int k = 0; k < 96; k++) a = fmaf(fw[k], seas_w[k * 1024 + m], a);
    g_Wt[m * 96 + j] = a;
}
__global__ void k0_fold2(const float* __restrict__ tr_w, const float* __restrict__ fus_w) {
    int idx = blockIdx.x * 256 + threadIdx.x;       // 96*512
    int j = idx >> 9, m = idx & 511;
    const float* fw = fus_w + j * 192 + 96;
    float a = 0.f;
    #pragma unroll 8
    for (int k = 0; k < 96; k++) a = fmaf(fw[k], tr_w[k * 512 + m], a);
    g_Wt[(1024 + m) * 96 + j] = a;
}
__global__ void k0_cb(const float* __restrict__ fus_w, const float* __restrict__ fus_b,
                      const float* __restrict__ seas_b, const float* __restrict__ tr_b) {
    int j = threadIdx.x;
    float a = fus_b[j];
    for (int k = 0; k < 96; k++) {
        a = fmaf(fus_w[j * 192 + k], seas_b[k], a);
        a = fmaf(fus_w[j * 192 + 96 + k], tr_b[k], a);
    }
    g_cb[j] = a;
}

// ---------------- K1a: RevIN stats + segmented EMA + seasonal/trend + pooled ----------------
// 16 channels per block; grid (21, 64); 256 threads; dynamic smem 69632B -> 3 blocks/SM
__global__ void __launch_bounds__(256) k1a_prep(const float* __restrict__ x,
                                                const float* __restrict__ rev_w,
                                                const float* __restrict__ rev_b) {
    extern __shared__ float sm[];
    float* xb = sm;                 // [512][17]
    float* tb = sm + 512 * 17;      // [512][17]
    __shared__ float red_s[16][17], red_q[16][17], meanb[16], stdb[16];
    __shared__ float segend[8][17], carry[8][17];
    __shared__ float pw[65];
    int b = blockIdx.y;
    int c0 = blockIdx.x * 16;
    int t = threadIdx.x;
    int w = t >> 5, lane = t & 31;          // warp/lane (writeout)
    int ci16 = t & 15, g16 = t >> 4;        // 16-wide mapping (load/normalize)
    int c = c0 + ci16;
    bool cv = (c < C_);

    if (t == 0) {
        pw[0] = 1.f;
        for (int j = 1; j <= 64; j++) pw[j] = pw[j - 1] * 0.8f;
    }

    // load + per-channel partial sums (row-group g16 = 0..15)
    float s = 0.f, q = 0.f;
    for (int l = g16; l < L_; l += 16) {
        float v = cv ? x[((size_t)b * L_ + l) * C_ + c] : 0.f;
        xb[l * 17 + ci16] = v;
        s += v;
        q = fmaf(v, v, q);
    }
    red_s[g16][ci16] = s; red_q[g16][ci16] = q;
    __syncthreads();
    if (t < 16) {
        float ss = 0.f, qq = 0.f;
        #pragma unroll
        for (int i = 0; i < 16; i++) { ss += red_s[i][t]; qq += red_q[i][t]; }
        float mu = ss * (1.f / (float)L_);
        float v2 = fmaxf(qq - (float)L_ * mu * mu, 0.f);
        float sd = sqrtf(v2 * (1.f / (float)(L_ - 1))) + EPS_;
        meanb[t] = mu; stdb[t] = sd;
        if (c0 + t < C_) { int bc = b * C_ + c0 + t; g_mean[bc] = mu; g_std[bc] = sd; }
    }
    __syncthreads();
    {
        float rw = cv ? rev_w[c] : 1.f;
        float rb = cv ? rev_b[c] : 0.f;
        float mu = meanb[ci16], inv = 1.f / stdb[ci16];
        for (int l = g16; l < L_; l += 16) {
            float v = xb[l * 17 + ci16];
            xb[l * 17 + ci16] = fmaf((v - mu) * inv, rw, rb);
        }
    }
    __syncthreads();
    // Phase A: threads 0..127 = (seg = t>>4, ci = t&15), 64-step provisional scan
    if (t < 128) {
        int seg = t >> 4;
        int base = seg * 64;
        float cl;
        if (seg == 0) {
            cl = xb[ci16];
            tb[ci16] = cl;
            #pragma unroll 4
            for (int l = 1; l < 64; l++) {
                cl = fmaf(0.8f, cl, 0.2f * xb[l * 17 + ci16]);
                tb[l * 17 + ci16] = cl;
            }
        } else {
            cl = 0.f;
            #pragma unroll 4
            for (int j = 0; j < 64; j++) {
                int l = base + j;
                cl = fmaf(0.8f, cl, 0.2f * xb[l * 17 + ci16]);
                tb[l * 17 + ci16] = cl;
            }
        }
        segend[seg][ci16] = cl;
    }
    __syncthreads();
    // Phase B: threads 0..15 propagate carries per channel
    if (t < 16) {
        float cacc = segend[0][t];
        carry[1][t] = cacc;
        float q64 = pw[64];
        #pragma unroll
        for (int s2 = 1; s2 <= 6; s2++) {
            cacc = fmaf(q64, cacc, segend[s2][t]);
            carry[s2 + 1][t] = cacc;
        }
    }
    __syncthreads();
    // Phase C: apply correction + seasonal
    if (t < 128) {
        int seg = t >> 4;
        int base = seg * 64;
        float cin = (seg == 0) ? 0.f : carry[seg][ci16];
        #pragma unroll 4
        for (int j = 0; j < 64; j++) {
            int l = base + j;
            float tf = fmaf(pw[j + 1], cin, tb[l * 17 + ci16]);
            tb[l * 17 + ci16] = tf;
            xb[l * 17 + ci16] = xb[l * 17 + ci16] - tf;
        }
    }
    __syncthreads();
    // writeout: warp = channel (w, w+8), lane covers l
    for (int ci = w; ci < 16; ci += 8) {
        int cc = c0 + ci;
        if (cc >= C_) continue;
        size_t bc = (size_t)b * C_ + cc;
        float* gs = g_s + bc * LP;
        float* gt = g_trend + bc * (size_t)L_;
        for (int l0 = 0; l0 < L_; l0 += 32) {
            gs[l0 + lane] = xb[(l0 + lane) * 17 + ci];
            gt[l0 + lane] = tb[(l0 + lane) * 17 + ci];
        }
        if (lane < 8) gs[L_ + lane] = xb[511 * 17 + ci];
        #pragma unroll
        for (int nn = 0; nn < 2; nn++) {
            int n = 2 * lane + nn;
            float sum = 0.f;
            #pragma unroll
            for (int p = 0; p < 16; p++) {
                int l = n * 8 + p;
                if (l > 511) l = 511;
                sum += xb[l * 17 + ci];
            }
            g_pool[bc * 64 + n] = sum * (1.f / 16.f);
        }
    }
}

// ---------------- K1b: fc1 + gelu -> g_h ([bc][j][n]); bn1 per-n partials ----------------
__global__ void __launch_bounds__(256) k1b_fc1(const float* __restrict__ fc1_w,
                                               const float* __restrict__ fc1_b) {
    __shared__ float s_sm[16 * LP];       // 33280B
    __shared__ float wt[512];             // wt[p*32+j] = fc1_w[j*16+p]
    __shared__ float stage[32 * 65];      // [j][n] padded
    int t = threadIdx.x;
    int w = t >> 5, lane = t & 31;
    size_t bc0 = (size_t)blockIdx.x * 16;
    for (int i = t; i < 512; i += 256) {
        int p = i >> 5, j = i & 31;
        wt[i] = fc1_w[j * 16 + p];
    }
    for (int i = t; i < 16 * LP; i += 256) s_sm[i] = g_s[bc0 * LP + i];
    __syncthreads();
    float wj[16];
    #pragma unroll
    for (int p = 0; p < 16; p++) wj[p] = wt[p * 32 + lane];
    float bj = fc1_b[lane];
    float ps[8], pq[8];
    #pragma unroll
    for (int i = 0; i < 8; i++) { ps[i] = 0.f; pq[i] = 0.f; }

    for (int r = 0; r < 16; r++) {
        const float* sp = s_sm + r * LP;
        #pragma unroll
        for (int nn = 0; nn < 8; nn++) {
            int n = nn * 8 + w;
            const float4* pv4 = (const float4*)(sp + n * 8);
            float4 f0 = pv4[0], f1 = pv4[1], f2 = pv4[2], f3 = pv4[3];
            float acc = bj;
            acc = fmaf(f0.x, wj[0], acc);
            acc = fmaf(f0.y, wj[1], acc);
            acc = fmaf(f0.z, wj[2], acc);
            acc = fmaf(f0.w, wj[3], acc);
            acc = fmaf(f1.x, wj[4], acc);
            acc = fmaf(f1.y, wj[5], acc);
            acc = fmaf(f1.z, wj[6], acc);
            acc = fmaf(f1.w, wj[7], acc);
            acc = fmaf(f2.x, wj[8], acc);
            acc = fmaf(f2.y, wj[9], acc);
            acc = fmaf(f2.z, wj[10], acc);
            acc = fmaf(f2.w, wj[11], acc);
            acc = fmaf(f3.x, wj[12], acc);
            acc = fmaf(f3.y, wj[13], acc);
            acc = fmaf(f3.z, wj[14], acc);
            acc = fmaf(f3.w, wj[15], acc);
            float g = geluf(acc);
            ps[nn] += g;
            pq[nn] = fmaf(g, g, pq[nn]);
            stage[lane * 65 + n] = g;
        }
        __syncthreads();
        float* dst = g_h + (bc0 + r) * 2048;
        for (int i = t; i < 2048; i += 256)
            dst[i] = stage[(i >> 6) * 65 + (i & 63)];
        __syncthreads();
    }
    #pragma unroll
    for (int nn = 0; nn < 8; nn++) {
        float s = ps[nn], q = pq[nn];
        #pragma unroll
        for (int off = 16; off; off >>= 1) {
            s += __shfl_down_sync(0xffffffff, s, off);
            q += __shfl_down_sync(0xffffffff, q, off);
        }
        if (lane == 0) {
            int n = nn * 8 + w;
            g_p1s[blockIdx.x * 64 + n] = s;
            g_p1q[blockIdx.x * 64 + n] = q;
        }
    }
}

// ---------------- K3/K5: reduce bn partials ----------------
__global__ void __launch_bounds__(1024) k3_stats1(const float* __restrict__ bn_w,
                                                  const float* __restrict__ bn_b) {
    __shared__ float ss[1024], qq[1024];
    int t = threadIdx.x;
    int n = t & 63, part = t >> 6;
    float s = 0.f, q = 0.f;
    for (int blk = part; blk < NB1; blk += 16) { s += g_p1s[blk * 64 + n]; q += g_p1q[blk * 64 + n]; }
    ss[t] = s; qq[t] = q;
    __syncthreads();
    if (t < 64) {
        float S = 0.f, Q = 0.f;
        #pragma unroll
        for (int i = 0; i < 16; i++) { S += ss[t + 64 * i]; Q += qq[t + 64 * i]; }
        float inv = 1.f / CNT_BN;
        float mu = S * inv;
        float var = fmaxf(Q * inv - mu * mu, 0.f);
        float sc = bn_w[t] * rsqrtf(var + EPS_);
        g_sc1[t] = sc;
        g_bi1[t] = fmaf(-mu, sc, bn_b[t]);
    }
}
__global__ void __launch_bounds__(1024) k5_stats2(const float* __restrict__ bn_w,
                                                  const float* __restrict__ bn_b) {
    __shared__ float ss[1024], qq[1024];
    int t = threadIdx.x;
    int n = t & 63, part = t >> 6;
    float s = 0.f, q = 0.f;
    for (int blk = part; blk < NB1; blk += 16) { s += g_p2s[blk * 64 + n]; q += g_p2q[blk * 64 + n]; }
    ss[t] = s; qq[t] = q;
    __syncthreads();
    if (t < 64) {
        float S = 0.f, Q = 0.f;
        #pragma unroll
        for (int i = 0; i < 16; i++) { S += ss[t + 64 * i]; Q += qq[t + 64 * i]; }
        float inv = 1.f / CNT_BN;
        float mu = S * inv;
        float var = fmaxf(Q * inv - mu * mu, 0.f);
        float sc = bn_w[t] * rsqrtf(var + EPS_);
        g_sc2[t] = sc;
        g_bi2[t] = fmaf(-mu, sc, bn_b[t]);
    }
}

// ---------------- K4: read g_h, bn1 affine + conv3 + gelu; bn2 partials ----------------
__global__ void __launch_bounds__(256) k4_conv(const float* __restrict__ conv_w,
                                               const float* __restrict__ conv_b) {
    __shared__ float rs[256], rq[256];
    int t = threadIdx.x;
    size_t bc0 = (size_t)blockIdx.x * 16;
    int n = t & 63;
    float sc = g_sc1[n], bi = g_bi1[n];
    float c0 = conv_w[n * 3], c1 = conv_w[n * 3 + 1], c2 = conv_w[n * 3 + 2];
    float cbv = conv_b[n];
    float psum = 0.f, psq = 0.f;
    #pragma unroll
    for (int q = 0; q < 4; q++) {
        int pair = t + 256 * q;
        int row = pair >> 6;
        const float* hp = g_h + (bc0 + row) * 2048 + n;
        float a[34];
        a[0] = 0.f; a[33] = 0.f;
        #pragma unroll
        for (int j = 0; j < 32; j++) a[j + 1] = fmaf(hp[j * 64], sc, bi);
        #pragma unroll
        for (int j = 0; j < 32; j++) {
            float vv = cbv;
            vv = fmaf(a[j], c0, vv);
            vv = fmaf(a[j + 1], c1, vv);
            vv = fmaf(a[j + 2], c2, vv);
            float g = geluf(vv);
            psum += g;
            psq = fmaf(g, g, psq);
        }
    }
    rs[t] = psum; rq[t] = psq;
    __syncthreads();
    if (t < 64) {
        float S = rs[t] + rs[t + 64] + rs[t + 128] + rs[t + 192];
        float Q = rq[t] + rq[t + 64] + rq[t + 128] + rq[t + 192];
        g_p2s[blockIdx.x * 64 + t] = S;
        g_p2q[blockIdx.x * 64 + t] = Q;
    }
}

// ---------------- Kg: gating MLP, 4 rows/warp batched (weight-LDS reuse) ----------------
__global__ void __launch_bounds__(256) kg_gate(const float* __restrict__ m1_w,
                                               const float* __restrict__ m1_b,
                                               const float* __restrict__ m2_w,
                                               const float* __restrict__ m2_b) {
    extern __shared__ float kg_sm[];
    float* m1p = kg_sm;                 // 8320
    float* m2t = kg_sm + 8320;          // 8192
    float* ps  = kg_sm + 16512;         // 2048
    float* us  = kg_sm + 18560;         // 4096
    int t = threadIdx.x;
    int w = t >> 5, lane = t & 31;
    size_t bc0 = (size_t)blockIdx.x * 32;
    for (int i = t; i < 8192; i += 256) {
        int h = i >> 6, k = i & 63;
        m1p[h * 65 + k] = m1_w[i];
    }
    for (int i = t; i < 8192; i += 256) {
        int nn = i >> 7, h = i & 127;
        m2t[h * 64 + nn] = m2_w[i];
    }
    for (int i = t; i < 2048; i += 256)
        ps[i] = g_pool[bc0 * 64 + i];
    __syncthreads();
    int r0 = w * 4;
    float u[4][4];
    {
        float b0 = m1_b[lane], b1 = m1_b[lane + 32], b2 = m1_b[lane + 64], b3 = m1_b[lane + 96];
        #pragma unroll
        for (int r = 0; r < 4; r++) { u[r][0] = b0; u[r][1] = b1; u[r][2] = b2; u[r][3] = b3; }
    }
    #pragma unroll 4
    for (int k = 0; k < 64; k++) {
        float wv0 = m1p[lane * 65 + k];
        float wv1 = m1p[(lane + 32) * 65 + k];
        float wv2 = m1p[(lane + 64) * 65 + k];
        float wv3 = m1p[(lane + 96) * 65 + k];
        #pragma unroll
        for (int r = 0; r < 4; r++) {
            float pk = ps[(r0 + r) * 64 + k];
            u[r][0] = fmaf(pk, wv0, u[r][0]);
            u[r][1] = fmaf(pk, wv1, u[r][1]);
            u[r][2] = fmaf(pk, wv2, u[r][2]);
            u[r][3] = fmaf(pk, wv3, u[r][3]);
        }
    }
    #pragma unroll
    for (int r = 0; r < 4; r++) {
        float* uwr = us + (r0 + r) * 128;
        uwr[lane] = geluf(u[r][0]);
        uwr[lane + 32] = geluf(u[r][1]);
        uwr[lane + 64] = geluf(u[r][2]);
        uwr[lane + 96] = geluf(u[r][3]);
    }
    __syncwarp();
    float acc[4][2];
    {
        float b0 = m2_b[lane], b1 = m2_b[lane + 32];
        #pragma unroll
        for (int r = 0; r < 4; r++) { acc[r][0] = b0; acc[r][1] = b1; }
    }
    #pragma unroll 4
    for (int h = 0; h < 128; h++) {
        float w0 = m2t[h * 64 + lane];
        float w1 = m2t[h * 64 + lane + 32];
        #pragma unroll
        for (int r = 0; r < 4; r++) {
            float uh = us[(r0 + r) * 128 + h];
            acc[r][0] = fmaf(uh, w0, acc[r][0]);
            acc[r][1] = fmaf(uh, w1, acc[r][1]);
        }
    }
    #pragma unroll
    for (int r = 0; r < 4; r++) {
        g_w[(bc0 + r0 + r) * 64 + lane] = sigf(acc[r][0]);
        g_w[(bc0 + r0 + r) * 64 + lane + 32] = sigf(acc[r][1]);
    }
}

// ---------------- K6: read g_h, chain conv/bn2/fc2 + combine + LN -> g_y (staged stores) ----------------
__global__ void __launch_bounds__(256) k6_local(const float* __restrict__ conv_w,
                                                const float* __restrict__ conv_b,
                                                const float* __restrict__ fc2_w,
                                                const float* __restrict__ fc2_b,
                                                const float* __restrict__ gl_scale,
                                                const float* __restrict__ ln_w,
                                                const float* __restrict__ ln_b) {
    extern __shared__ float k6_sm[];
    float* s_sm = k6_sm;                       // 8320 floats
    float* w2 = k6_sm + 16 * LP;               // 512
    float* ystage = k6_sm + 16 * LP + 512;     // 4*1088 = 4352
    __shared__ float b2[16], lw[16], lb[16];
    int t = threadIdx.x;
    size_t bc0 = (size_t)blockIdx.x * 16;
    w2[t] = fc2_w[t];
    w2[t + 256] = fc2_w[t + 256];
    if (t < 16) { b2[t] = fc2_b[t]; lw[t] = ln_w[t]; lb[t] = ln_b[t]; }
    for (int i = t; i < 16 * LP; i += 256) s_sm[i] = g_s[bc0 * LP + i];
    __syncthreads();
    float gs = gl_scale[0];
    int n = t & 63;
    float sc1v = g_sc1[n], bi1v = g_bi1[n];
    float sc2v = g_sc2[n], bi2v = g_bi2[n];
    float c0 = conv_w[n * 3], c1 = conv_w[n * 3 + 1], c2 = conv_w[n * 3 + 2];
    float cbv = conv_b[n];
    #pragma unroll
    for (int q = 0; q < 4; q++) {
        int pair = t + 256 * q;
        int row = pair >> 6;
        int r4 = row & 3;
        size_t bc = bc0 + row;
        const float* hp = g_h + bc * 2048 + n;
        float a[34];
        a[0] = 0.f; a[33] = 0.f;
        #pragma unroll
        for (int j = 0; j < 32; j++) a[j + 1] = fmaf(hp[j * 64], sc1v, bi1v);
        float left = 0.f;
        #pragma unroll
        for (int j = 0; j < 32; j++) {
            float cur = a[j + 1];
            float vv = cbv;
            vv = fmaf(left, c0, vv);
            vv = fmaf(cur, c1, vv);
            vv = fmaf(a[j + 2], c2, vv);
            left = cur;
            a[j + 1] = fmaf(geluf(vv), sc2v, bi2v);
        }
        float p[16];
        const float4* spp = (const float4*)(s_sm + row * LP + n * 8);
        #pragma unroll
        for (int v = 0; v < 4; v++) {
            float4 f = spp[v];
            p[4 * v] = f.x; p[4 * v + 1] = f.y; p[4 * v + 2] = f.z; p[4 * v + 3] = f.w;
        }
        float wv = g_w[bc * 64 + n];
        float m3 = fmaf(gs, wv, 3.f);
        float y[16];
        float musum = 0.f;
        #pragma unroll
        for (int pp = 0; pp < 16; pp++) {
            float acc = b2[pp];
            const float4* wp = (const float4*)(w2 + pp * 32);
            #pragma unroll
            for (int j = 0; j < 8; j++) {
                float4 f = wp[j];
                acc = fmaf(a[4 * j + 1], f.x, acc);
                acc = fmaf(a[4 * j + 2], f.y, acc);
                acc = fmaf(a[4 * j + 3], f.z, acc);
                acc = fmaf(a[4 * j + 4], f.w, acc);
            }
            float yy = fmaf(p[pp], m3, acc);
            y[pp] = yy;
            musum += yy;
        }
        float mu = musum * (1.f / 16.f);
        float s2 = 0.f;
        #pragma unroll
        for (int pp = 0; pp < 16; pp++) { float d = y[pp] - mu; s2 = fmaf(d, d, s2); }
        float r = rsqrtf(s2 * (1.f / 16.f) + EPS_);
        float* yst = ystage + r4 * 1088 + n * 17;
        #pragma unroll
        for (int pp = 0; pp < 16; pp++)
            yst[pp] = fmaf((y[pp] - mu) * r, lw[pp], lb[pp]);
        __syncthreads();
        {
            float* gyb = g_y + (bc0 + (size_t)q * 4) * 1024;
            for (int i = t; i < 4096; i += 256) {
                int rr = i >> 10, k = i & 1023;
                gyb[rr * 1024 + k] = ystage[rr * 1088 + (k >> 4) * 17 + (k & 15)];
            }
        }
        __syncthreads();
    }
}

// ---------------- K7: fused final GEMM + un-RevIN + transpose (R11 config) ----------------
__global__ void __launch_bounds__(128) k7_gemm(const float* __restrict__ rev_w,
                                               const float* __restrict__ rev_b,
                                               float* __restrict__ out) {
    __shared__ float As[2][64 * 20];
    __shared__ float Bs[2][16 * 96];
    int t = threadIdx.x;
    size_t bc0 = (size_t)blockIdx.x * 64;
    int ty = t >> 4, tx = t & 15;
    int r0 = ty * 8, c0l = tx * 6;

    int lr = t >> 1, lk = (t & 1) * 8;
    int bk = t >> 3, bo = (t & 7) * 12;

    uint32_t as_sm[2], bs_sm[2];
    as_sm[0] = (uint32_t)__cvta_generic_to_shared(&As[0][0]);
    as_sm[1] = (uint32_t)__cvta_generic_to_shared(&As[1][0]);
    bs_sm[0] = (uint32_t)__cvta_generic_to_shared(&Bs[0][0]);
    bs_sm[1] = (uint32_t)__cvta_generic_to_shared(&Bs[1][0]);

    float acc[8][6];
    #pragma unroll
    for (int i = 0; i < 8; i++)
        #pragma unroll
        for (int j = 0; j < 6; j++) acc[i][j] = 0.f;

    auto load_tile = [&](int it, int bu) {
        int k0 = it * 16;
        const float* srcrow;
        if (k0 < 1024) srcrow = g_y + (bc0 + lr) * 1024 + k0 + lk;
        else           srcrow = g_trend + (bc0 + lr) * 512 + (k0 - 1024) + lk;
        uint32_t d = as_sm[bu] + (uint32_t)((lr * 20 + lk) * 4);
        cpa16(d, srcrow);
        cpa16(d + 16, srcrow + 4);
        const float* bsrc = g_Wt + (k0 + bk) * 96 + bo;
        #pragma unroll
        for (int i = 0; i < 3; i++)
            cpa16(bs_sm[bu] + (uint32_t)((bk * 96 + bo + 4 * i) * 4), bsrc + 4 * i);
    };

    load_tile(0, 0);
    cp_commit();
    for (int it = 0; it < 96; it++) {
        int cur = it & 1;
        if (it + 1 < 96) {
            load_tile(it + 1, cur ^ 1);
            cp_commit();
            asm volatile("cp.async.wait_group 1;\n" ::: "memory");
        } else {
            asm volatile("cp.async.wait_group 0;\n" ::: "memory");
        }
        __syncthreads();
        #pragma unroll
        for (int k = 0; k < 16; k++) {
            float a8[8];
            #pragma unroll
            for (int i = 0; i < 8; i++) a8[i] = As[cur][(r0 + i) * 20 + k];
            const float* bp = &Bs[cur][k * 96 + c0l];
            float b6[6];
            #pragma unroll
            for (int j = 0; j < 6; j++) b6[j] = bp[j];
            #pragma unroll
            for (int i = 0; i < 8; i++)
                #pragma unroll
                for (int j = 0; j < 6; j++)
                    acc[i][j] = fmaf(a8[i], b6[j], acc[i][j]);
        }
        __syncthreads();
    }
    #pragma unroll
    for (int i = 0; i < 8; i++) {
        size_t bc = bc0 + r0 + i;
        int b = (int)(bc / C_);
        int c = (int)(bc - (size_t)b * C_);
        float rw = rev_w[c], rb = rev_b[c];
        float sd = g_std[bc], mn = g_mean[bc];
        #pragma unroll
        for (int j = 0; j < 6; j++) {
            int col = c0l + j;
            float v = acc[i][j] + g_cb[col];
            v = fmaf((v - rb) / rw, sd, mn);
            out[((size_t)b * PRED_ + col) * C_ + c] = v;
        }
    }
}

// ---------------- launch ----------------
extern "C" void kernel_launch(void* const* d_in, const int* in_sizes, int n_in,
                              void* d_out, int out_size) {
    const float* x       = (const float*)d_in[0];
    const float* rev_w   = (const float*)d_in[1];
    const float* rev_b   = (const float*)d_in[2];
    const float* fc1_w   = (const float*)d_in[3];
    const float* fc1_b   = (const float*)d_in[4];
    const float* bn1_w   = (const float*)d_in[5];
    const float* bn1_b   = (const float*)d_in[6];
    const float* conv_w  = (const float*)d_in[7];
    const float* conv_b  = (const float*)d_in[8];
    const float* bn2_w   = (const float*)d_in[9];
    const float* bn2_b   = (const float*)d_in[10];
    const float* fc2_w   = (const float*)d_in[11];
    const float* fc2_b   = (const float*)d_in[12];
    const float* m1_w    = (const float*)d_in[13];
    const float* m1_b    = (const float*)d_in[14];
    const float* m2_w    = (const float*)d_in[15];
    const float* m2_b    = (const float*)d_in[16];
    const float* gl_sc   = (const float*)d_in[17];
    const float* ln_w    = (const float*)d_in[18];
    const float* ln_b    = (const float*)d_in[19];
    const float* seas_w  = (const float*)d_in[20];
    const float* seas_b  = (const float*)d_in[21];
    const float* tr_w    = (const float*)d_in[22];
    const float* tr_b    = (const float*)d_in[23];
    const float* fus_w   = (const float*)d_in[24];
    const float* fus_b   = (const float*)d_in[25];
    float* out = (float*)d_out;

    const int K1_SMEM = 512 * 17 * 2 * sizeof(float);   // 69632
    const int KG_SMEM = 22656 * sizeof(float);           // 90624
    const int K6_SMEM = (16 * LP + 512 + 4 * 1088) * sizeof(float);
    cudaFuncSetAttribute(k1a_prep, cudaFuncAttributeMaxDynamicSharedMemorySize, K1_SMEM);
    cudaFuncSetAttribute(kg_gate, cudaFuncAttributeMaxDynamicSharedMemorySize, KG_SMEM);
    cudaFuncSetAttribute(k6_local, cudaFuncAttributeMaxDynamicSharedMemorySize, K6_SMEM);

    k0_fold1<<<384, 256>>>(seas_w, fus_w);                        // 1
    k0_fold2<<<192, 256>>>(tr_w, fus_w);                          // 2
    k0_cb<<<1, 96>>>(fus_w, fus_b, seas_b, tr_b);                 // 3
    k1a_prep<<<dim3(21, 64), 256, K1_SMEM>>>(x, rev_w, rev_b);   // 4 -> profiled
    k1b_fc1<<<NB1, 256>>>(fc1_w, fc1_b);
    k3_stats1<<<1, 1024>>>(bn1_w, bn1_b);
    k4_conv<<<NB1, 256>>>(conv_w, conv_b);
    k5_stats2<<<1, 1024>>>(bn2_w, bn2_b);
    kg_gate<<<642, 256, KG_SMEM>>>(m1_w, m1_b, m2_w, m2_b);
    k6_local<<<NB1, 256, K6_SMEM>>>(conv_w, conv_b, fc2_w, fc2_b, gl_sc, ln_w, ln_b);
    k7_gemm<<<321, 128>>>(rev_w, rev_b, out);
    (void)in_sizes; (void)n_in; (void)out_size;
}

// round 16
// speedup vs baseline: 1.2813x; 1.1692x over previous
#include <cuda_runtime.h>
#include <cuda_bf16.h>
#include <math.h>
#include <stdint.h>
#include <stddef.h>

#define B_ 64
#define L_ 512
#define C_ 321
#define BC 20544            // B_*C_
#define PRED_ 96
#define LP 520              // L + STRIDE
#define NB1 1284            // BC/16 blocks (k1b/k4/k6)
#define CNT_BN 657408.0f    // BC*32
#define EPS_ 1e-5f

// ---------------- scratch (__device__ globals; no runtime allocation) ----------------
static __device__ float g_s[(size_t)BC * LP];        // seasonal, padded
static __device__ float g_trend[(size_t)BC * L_];    // trend rows [bc][L]  (tf32-truncated)
static __device__ float g_mean[BC];
static __device__ float g_std[BC];
static __device__ float g_h[(size_t)BC * 2048];      // h1 = gelu(fc1), layout [bc][j(32)][n(64)]
static __device__ float g_y[(size_t)BC * 1024];      // post-LN y [bc][1024]  (tf32-truncated)
static __device__ float g_pool[(size_t)BC * 64];     // sp.mean(-1)
static __device__ float g_w[(size_t)BC * 64];        // gating sigmoid output
static __device__ float g_Wt[1536 * 96];             // folded weights, [k][j]  (tf32-truncated)
static __device__ float g_cb[96];                    // folded bias (fp32 exact)
static __device__ float g_p1s[NB1 * 64];
static __device__ float g_p1q[NB1 * 64];
static __device__ float g_p2s[NB1 * 64];
static __device__ float g_p2q[NB1 * 64];
static __device__ float g_sc1[64], g_bi1[64], g_sc2[64], g_bi2[64];

__device__ __forceinline__ float geluf(float v) {
    return 0.5f * v * (1.0f + erff(v * 0.70710678f));
}
__device__ __forceinline__ float sigf(float v) {
    return 1.0f / (1.0f + expf(-v));
}
__device__ __forceinline__ float to_tf32(float v) {
    uint32_t r;
    asm("cvt.rna.tf32.f32 %0, %1;" : "=r"(r) : "f"(v));
    return __uint_as_float(r);
}

// cp.async helpers (LDGSTS)
__device__ __forceinline__ void cpa16(uint32_t d, const float* s) {
    asm volatile("cp.async.ca.shared.global [%0], [%1], 16;\n" :: "r"(d), "l"(s));
}
__device__ __forceinline__ void cp_commit() {
    asm volatile("cp.async.commit_group;\n" ::: "memory");
}

// ---------------- K0: fold fusion layer (tf32-truncated output for k7) ----------------
__global__ void k0_fold1(const float* __restrict__ seas_w, const float* __restrict__ fus_w) {
    int idx = blockIdx.x * 256 + threadIdx.x;       // 96*1024
    int j = idx >> 10, m = idx & 1023;
    const float* fw = fus_w + j * 192;
    float a = 0.f;
    #pragma unroll 8
    for (int k = 0; k < 96; k++) a = fmaf(fw[k], seas_w[k * 1024 + m], a);
    g_Wt[m * 96 + j] = to_tf32(a);
}
__global__ void k0_fold2(const float* __restrict__ tr_w, const float* __restrict__ fus_w) {
    int idx = blockIdx.x * 256 + threadIdx.x;       // 96*512
    int j = idx >> 9, m = idx & 511;
    const float* fw = fus_w + j * 192 + 96;
    float a = 0.f;
    #pragma unroll 8
    for (int k = 0; k < 96; k++) a = fmaf(fw[k], tr_w[k * 512 + m], a);
    g_Wt[(1024 + m) * 96 + j] = to_tf32(a);
}
__global__ void k0_cb(const float* __restrict__ fus_w, const float* __restrict__ fus_b,
                      const float* __restrict__ seas_b, const float* __restrict__ tr_b) {
    int j = threadIdx.x;
    float a = fus_b[j];
    for (int k = 0; k < 96; k++) {
        a = fmaf(fus_w[j * 192 + k], seas_b[k], a);
        a = fmaf(fus_w[j * 192 + 96 + k], tr_b[k], a);
    }
    g_cb[j] = a;
}

// ---------------- K1a: RevIN stats + segmented EMA + seasonal/trend + pooled ----------------
// 16 channels per block; grid (21, 64); 256 threads; dynamic smem 69632B
__global__ void __launch_bounds__(256) k1a_prep(const float* __restrict__ x,
                                                const float* __restrict__ rev_w,
                                                const float* __restrict__ rev_b) {
    extern __shared__ float sm[];
    float* xb = sm;                 // [512][17]
    float* tb = sm + 512 * 17;      // [512][17]
    __shared__ float red_s[16][17], red_q[16][17], meanb[16], stdb[16];
    __shared__ float segend[8][17], carry[8][17];
    __shared__ float pw[65];
    int b = blockIdx.y;
    int c0 = blockIdx.x * 16;
    int t = threadIdx.x;
    int w = t >> 5, lane = t & 31;
    int ci16 = t & 15, g16 = t >> 4;
    int c = c0 + ci16;
    bool cv = (c < C_);

    if (t == 0) {
        pw[0] = 1.f;
        for (int j = 1; j <= 64; j++) pw[j] = pw[j - 1] * 0.8f;
    }

    float s = 0.f, q = 0.f;
    for (int l = g16; l < L_; l += 16) {
        float v = cv ? x[((size_t)b * L_ + l) * C_ + c] : 0.f;
        xb[l * 17 + ci16] = v;
        s += v;
        q = fmaf(v, v, q);
    }
    red_s[g16][ci16] = s; red_q[g16][ci16] = q;
    __syncthreads();
    if (t < 16) {
        float ss = 0.f, qq = 0.f;
        #pragma unroll
        for (int i = 0; i < 16; i++) { ss += red_s[i][t]; qq += red_q[i][t]; }
        float mu = ss * (1.f / (float)L_);
        float v2 = fmaxf(qq - (float)L_ * mu * mu, 0.f);
        float sd = sqrtf(v2 * (1.f / (float)(L_ - 1))) + EPS_;
        meanb[t] = mu; stdb[t] = sd;
        if (c0 + t < C_) { int bc = b * C_ + c0 + t; g_mean[bc] = mu; g_std[bc] = sd; }
    }
    __syncthreads();
    {
        float rw = cv ? rev_w[c] : 1.f;
        float rb = cv ? rev_b[c] : 0.f;
        float mu = meanb[ci16], inv = 1.f / stdb[ci16];
        for (int l = g16; l < L_; l += 16) {
            float v = xb[l * 17 + ci16];
            xb[l * 17 + ci16] = fmaf((v - mu) * inv, rw, rb);
        }
    }
    __syncthreads();
    if (t < 128) {
        int seg = t >> 4;
        int base = seg * 64;
        float cl;
        if (seg == 0) {
            cl = xb[ci16];
            tb[ci16] = cl;
            #pragma unroll 4
            for (int l = 1; l < 64; l++) {
                cl = fmaf(0.8f, cl, 0.2f * xb[l * 17 + ci16]);
                tb[l * 17 + ci16] = cl;
            }
        } else {
            cl = 0.f;
            #pragma unroll 4
            for (int j = 0; j < 64; j++) {
                int l = base + j;
                cl = fmaf(0.8f, cl, 0.2f * xb[l * 17 + ci16]);
                tb[l * 17 + ci16] = cl;
            }
        }
        segend[seg][ci16] = cl;
    }
    __syncthreads();
    if (t < 16) {
        float cacc = segend[0][t];
        carry[1][t] = cacc;
        float q64 = pw[64];
        #pragma unroll
        for (int s2 = 1; s2 <= 6; s2++) {
            cacc = fmaf(q64, cacc, segend[s2][t]);
            carry[s2 + 1][t] = cacc;
        }
    }
    __syncthreads();
    if (t < 128) {
        int seg = t >> 4;
        int base = seg * 64;
        float cin = (seg == 0) ? 0.f : carry[seg][ci16];
        #pragma unroll 4
        for (int j = 0; j < 64; j++) {
            int l = base + j;
            float tf = fmaf(pw[j + 1], cin, tb[l * 17 + ci16]);
            tb[l * 17 + ci16] = tf;
            xb[l * 17 + ci16] = xb[l * 17 + ci16] - tf;
        }
    }
    __syncthreads();
    for (int ci = w; ci < 16; ci += 8) {
        int cc = c0 + ci;
        if (cc >= C_) continue;
        size_t bc = (size_t)b * C_ + cc;
        float* gs = g_s + bc * LP;
        float* gt = g_trend + bc * (size_t)L_;
        for (int l0 = 0; l0 < L_; l0 += 32) {
            gs[l0 + lane] = xb[(l0 + lane) * 17 + ci];
            gt[l0 + lane] = to_tf32(tb[(l0 + lane) * 17 + ci]);   // k7-only consumer
        }
        if (lane < 8) gs[L_ + lane] = xb[511 * 17 + ci];
        #pragma unroll
        for (int nn = 0; nn < 2; nn++) {
            int n = 2 * lane + nn;
            float sum = 0.f;
            #pragma unroll
            for (int p = 0; p < 16; p++) {
                int l = n * 8 + p;
                if (l > 511) l = 511;
                sum += xb[l * 17 + ci];
            }
            g_pool[bc * 64 + n] = sum * (1.f / 16.f);
        }
    }
}

// ---------------- K1b: fc1 + gelu -> g_h ([bc][j][n]); bn1 per-n partials ----------------
__global__ void __launch_bounds__(256) k1b_fc1(const float* __restrict__ fc1_w,
                                               const float* __restrict__ fc1_b) {
    __shared__ float s_sm[16 * LP];
    __shared__ float wt[512];
    __shared__ float stage[32 * 65];
    int t = threadIdx.x;
    int w = t >> 5, lane = t & 31;
    size_t bc0 = (size_t)blockIdx.x * 16;
    for (int i = t; i < 512; i += 256) {
        int p = i >> 5, j = i & 31;
        wt[i] = fc1_w[j * 16 + p];
    }
    for (int i = t; i < 16 * LP; i += 256) s_sm[i] = g_s[bc0 * LP + i];
    __syncthreads();
    float wj[16];
    #pragma unroll
    for (int p = 0; p < 16; p++) wj[p] = wt[p * 32 + lane];
    float bj = fc1_b[lane];
    float ps[8], pq[8];
    #pragma unroll
    for (int i = 0; i < 8; i++) { ps[i] = 0.f; pq[i] = 0.f; }

    for (int r = 0; r < 16; r++) {
        const float* sp = s_sm + r * LP;
        #pragma unroll
        for (int nn = 0; nn < 8; nn++) {
            int n = nn * 8 + w;
            const float4* pv4 = (const float4*)(sp + n * 8);
            float4 f0 = pv4[0], f1 = pv4[1], f2 = pv4[2], f3 = pv4[3];
            float acc = bj;
            acc = fmaf(f0.x, wj[0], acc);
            acc = fmaf(f0.y, wj[1], acc);
            acc = fmaf(f0.z, wj[2], acc);
            acc = fmaf(f0.w, wj[3], acc);
            acc = fmaf(f1.x, wj[4], acc);
            acc = fmaf(f1.y, wj[5], acc);
            acc = fmaf(f1.z, wj[6], acc);
            acc = fmaf(f1.w, wj[7], acc);
            acc = fmaf(f2.x, wj[8], acc);
            acc = fmaf(f2.y, wj[9], acc);
            acc = fmaf(f2.z, wj[10], acc);
            acc = fmaf(f2.w, wj[11], acc);
            acc = fmaf(f3.x, wj[12], acc);
            acc = fmaf(f3.y, wj[13], acc);
            acc = fmaf(f3.z, wj[14], acc);
            acc = fmaf(f3.w, wj[15], acc);
            float g = geluf(acc);
            ps[nn] += g;
            pq[nn] = fmaf(g, g, pq[nn]);
            stage[lane * 65 + n] = g;
        }
        __syncthreads();
        float* dst = g_h + (bc0 + r) * 2048;
        for (int i = t; i < 2048; i += 256)
            dst[i] = stage[(i >> 6) * 65 + (i & 63)];
        __syncthreads();
    }
    #pragma unroll
    for (int nn = 0; nn < 8; nn++) {
        float s = ps[nn], q = pq[nn];
        #pragma unroll
        for (int off = 16; off; off >>= 1) {
            s += __shfl_down_sync(0xffffffff, s, off);
            q += __shfl_down_sync(0xffffffff, q, off);
        }
        if (lane == 0) {
            int n = nn * 8 + w;
            g_p1s[blockIdx.x * 64 + n] = s;
            g_p1q[blockIdx.x * 64 + n] = q;
        }
    }
}

// ---------------- K3/K5: reduce bn partials ----------------
__global__ void __launch_bounds__(1024) k3_stats1(const float* __restrict__ bn_w,
                                                  const float* __restrict__ bn_b) {
    __shared__ float ss[1024], qq[1024];
    int t = threadIdx.x;
    int n = t & 63, part = t >> 6;
    float s = 0.f, q = 0.f;
    for (int blk = part; blk < NB1; blk += 16) { s += g_p1s[blk * 64 + n]; q += g_p1q[blk * 64 + n]; }
    ss[t] = s; qq[t] = q;
    __syncthreads();
    if (t < 64) {
        float S = 0.f, Q = 0.f;
        #pragma unroll
        for (int i = 0; i < 16; i++) { S += ss[t + 64 * i]; Q += qq[t + 64 * i]; }
        float inv = 1.f / CNT_BN;
        float mu = S * inv;
        float var = fmaxf(Q * inv - mu * mu, 0.f);
        float sc = bn_w[t] * rsqrtf(var + EPS_);
        g_sc1[t] = sc;
        g_bi1[t] = fmaf(-mu, sc, bn_b[t]);
    }
}
__global__ void __launch_bounds__(1024) k5_stats2(const float* __restrict__ bn_w,
                                                  const float* __restrict__ bn_b) {
    __shared__ float ss[1024], qq[1024];
    int t = threadIdx.x;
    int n = t & 63, part = t >> 6;
    float s = 0.f, q = 0.f;
    for (int blk = part; blk < NB1; blk += 16) { s += g_p2s[blk * 64 + n]; q += g_p2q[blk * 64 + n]; }
    ss[t] = s; qq[t] = q;
    __syncthreads();
    if (t < 64) {
        float S = 0.f, Q = 0.f;
        #pragma unroll
        for (int i = 0; i < 16; i++) { S += ss[t + 64 * i]; Q += qq[t + 64 * i]; }
        float inv = 1.f / CNT_BN;
        float mu = S * inv;
        float var = fmaxf(Q * inv - mu * mu, 0.f);
        float sc = bn_w[t] * rsqrtf(var + EPS_);
        g_sc2[t] = sc;
        g_bi2[t] = fmaf(-mu, sc, bn_b[t]);
    }
}

// ---------------- K4: read g_h, bn1 affine + conv3 + gelu; bn2 partials ----------------
__global__ void __launch_bounds__(256) k4_conv(const float* __restrict__ conv_w,
                                               const float* __restrict__ conv_b) {
    __shared__ float rs[256], rq[256];
    int t = threadIdx.x;
    size_t bc0 = (size_t)blockIdx.x * 16;
    int n = t & 63;
    float sc = g_sc1[n], bi = g_bi1[n];
    float c0 = conv_w[n * 3], c1 = conv_w[n * 3 + 1], c2 = conv_w[n * 3 + 2];
    float cbv = conv_b[n];
    float psum = 0.f, psq = 0.f;
    #pragma unroll
    for (int q = 0; q < 4; q++) {
        int pair = t + 256 * q;
        int row = pair >> 6;
        const float* hp = g_h + (bc0 + row) * 2048 + n;
        float a[34];
        a[0] = 0.f; a[33] = 0.f;
        #pragma unroll
        for (int j = 0; j < 32; j++) a[j + 1] = fmaf(hp[j * 64], sc, bi);
        #pragma unroll
        for (int j = 0; j < 32; j++) {
            float vv = cbv;
            vv = fmaf(a[j], c0, vv);
            vv = fmaf(a[j + 1], c1, vv);
            vv = fmaf(a[j + 2], c2, vv);
            float g = geluf(vv);
            psum += g;
            psq = fmaf(g, g, psq);
        }
    }
    rs[t] = psum; rq[t] = psq;
    __syncthreads();
    if (t < 64) {
        float S = rs[t] + rs[t + 64] + rs[t + 128] + rs[t + 192];
        float Q = rq[t] + rq[t + 64] + rq[t + 128] + rq[t + 192];
        g_p2s[blockIdx.x * 64 + t] = S;
        g_p2q[blockIdx.x * 64 + t] = Q;
    }
}

// ---------------- Kg: gating MLP, 4 rows/warp batched ----------------
__global__ void __launch_bounds__(256) kg_gate(const float* __restrict__ m1_w,
                                               const float* __restrict__ m1_b,
                                               const float* __restrict__ m2_w,
                                               const float* __restrict__ m2_b) {
    extern __shared__ float kg_sm[];
    float* m1p = kg_sm;                 // 8320
    float* m2t = kg_sm + 8320;          // 8192
    float* ps  = kg_sm + 16512;         // 2048
    float* us  = kg_sm + 18560;         // 4096
    int t = threadIdx.x;
    int w = t >> 5, lane = t & 31;
    size_t bc0 = (size_t)blockIdx.x * 32;
    for (int i = t; i < 8192; i += 256) {
        int h = i >> 6, k = i & 63;
        m1p[h * 65 + k] = m1_w[i];
    }
    for (int i = t; i < 8192; i += 256) {
        int nn = i >> 7, h = i & 127;
        m2t[h * 64 + nn] = m2_w[i];
    }
    for (int i = t; i < 2048; i += 256)
        ps[i] = g_pool[bc0 * 64 + i];
    __syncthreads();
    int r0 = w * 4;
    float u[4][4];
    {
        float b0 = m1_b[lane], b1 = m1_b[lane + 32], b2 = m1_b[lane + 64], b3 = m1_b[lane + 96];
        #pragma unroll
        for (int r = 0; r < 4; r++) { u[r][0] = b0; u[r][1] = b1; u[r][2] = b2; u[r][3] = b3; }
    }
    #pragma unroll 4
    for (int k = 0; k < 64; k++) {
        float wv0 = m1p[lane * 65 + k];
        float wv1 = m1p[(lane + 32) * 65 + k];
        float wv2 = m1p[(lane + 64) * 65 + k];
        float wv3 = m1p[(lane + 96) * 65 + k];
        #pragma unroll
        for (int r = 0; r < 4; r++) {
            float pk = ps[(r0 + r) * 64 + k];
            u[r][0] = fmaf(pk, wv0, u[r][0]);
            u[r][1] = fmaf(pk, wv1, u[r][1]);
            u[r][2] = fmaf(pk, wv2, u[r][2]);
            u[r][3] = fmaf(pk, wv3, u[r][3]);
        }
    }
    #pragma unroll
    for (int r = 0; r < 4; r++) {
        float* uwr = us + (r0 + r) * 128;
        uwr[lane] = geluf(u[r][0]);
        uwr[lane + 32] = geluf(u[r][1]);
        uwr[lane + 64] = geluf(u[r][2]);
        uwr[lane + 96] = geluf(u[r][3]);
    }
    __syncwarp();
    float acc[4][2];
    {
        float b0 = m2_b[lane], b1 = m2_b[lane + 32];
        #pragma unroll
        for (int r = 0; r < 4; r++) { acc[r][0] = b0; acc[r][1] = b1; }
    }
    #pragma unroll 4
    for (int h = 0; h < 128; h++) {
        float w0 = m2t[h * 64 + lane];
        float w1 = m2t[h * 64 + lane + 32];
        #pragma unroll
        for (int r = 0; r < 4; r++) {
            float uh = us[(r0 + r) * 128 + h];
            acc[r][0] = fmaf(uh, w0, acc[r][0]);
            acc[r][1] = fmaf(uh, w1, acc[r][1]);
        }
    }
    #pragma unroll
    for (int r = 0; r < 4; r++) {
        g_w[(bc0 + r0 + r) * 64 + lane] = sigf(acc[r][0]);
        g_w[(bc0 + r0 + r) * 64 + lane + 32] = sigf(acc[r][1]);
    }
}

// ---------------- K6: read g_h, chain conv/bn2/fc2 + combine + LN -> g_y (tf32, staged) ----------------
__global__ void __launch_bounds__(256) k6_local(const float* __restrict__ conv_w,
                                                const float* __restrict__ conv_b,
                                                const float* __restrict__ fc2_w,
                                                const float* __restrict__ fc2_b,
                                                const float* __restrict__ gl_scale,
                                                const float* __restrict__ ln_w,
                                                const float* __restrict__ ln_b) {
    extern __shared__ float k6_sm[];
    float* s_sm = k6_sm;                       // 8320 floats
    float* w2 = k6_sm + 16 * LP;               // 512
    float* ystage = k6_sm + 16 * LP + 512;     // 4*1088
    __shared__ float b2[16], lw[16], lb[16];
    int t = threadIdx.x;
    size_t bc0 = (size_t)blockIdx.x * 16;
    w2[t] = fc2_w[t];
    w2[t + 256] = fc2_w[t + 256];
    if (t < 16) { b2[t] = fc2_b[t]; lw[t] = ln_w[t]; lb[t] = ln_b[t]; }
    for (int i = t; i < 16 * LP; i += 256) s_sm[i] = g_s[bc0 * LP + i];
    __syncthreads();
    float gs = gl_scale[0];
    int n = t & 63;
    float sc1v = g_sc1[n], bi1v = g_bi1[n];
    float sc2v = g_sc2[n], bi2v = g_bi2[n];
    float c0 = conv_w[n * 3], c1 = conv_w[n * 3 + 1], c2 = conv_w[n * 3 + 2];
    float cbv = conv_b[n];
    #pragma unroll
    for (int q = 0; q < 4; q++) {
        int pair = t + 256 * q;
        int row = pair >> 6;
        int r4 = row & 3;
        size_t bc = bc0 + row;
        const float* hp = g_h + bc * 2048 + n;
        float a[34];
        a[0] = 0.f; a[33] = 0.f;
        #pragma unroll
        for (int j = 0; j < 32; j++) a[j + 1] = fmaf(hp[j * 64], sc1v, bi1v);
        float left = 0.f;
        #pragma unroll
        for (int j = 0; j < 32; j++) {
            float cur = a[j + 1];
            float vv = cbv;
            vv = fmaf(left, c0, vv);
            vv = fmaf(cur, c1, vv);
            vv = fmaf(a[j + 2], c2, vv);
            left = cur;
            a[j + 1] = fmaf(geluf(vv), sc2v, bi2v);
        }
        float p[16];
        const float4* spp = (const float4*)(s_sm + row * LP + n * 8);
        #pragma unroll
        for (int v = 0; v < 4; v++) {
            float4 f = spp[v];
            p[4 * v] = f.x; p[4 * v + 1] = f.y; p[4 * v + 2] = f.z; p[4 * v + 3] = f.w;
        }
        float wv = g_w[bc * 64 + n];
        float m3 = fmaf(gs, wv, 3.f);
        float y[16];
        float musum = 0.f;
        #pragma unroll
        for (int pp = 0; pp < 16; pp++) {
            float acc = b2[pp];
            const float4* wp = (const float4*)(w2 + pp * 32);
            #pragma unroll
            for (int j = 0; j < 8; j++) {
                float4 f = wp[j];
                acc = fmaf(a[4 * j + 1], f.x, acc);
                acc = fmaf(a[4 * j + 2], f.y, acc);
                acc = fmaf(a[4 * j + 3], f.z, acc);
                acc = fmaf(a[4 * j + 4], f.w, acc);
            }
            float yy = fmaf(p[pp], m3, acc);
            y[pp] = yy;
            musum += yy;
        }
        float mu = musum * (1.f / 16.f);
        float s2 = 0.f;
        #pragma unroll
        for (int pp = 0; pp < 16; pp++) { float d = y[pp] - mu; s2 = fmaf(d, d, s2); }
        float r = rsqrtf(s2 * (1.f / 16.f) + EPS_);
        float* yst = ystage + r4 * 1088 + n * 17;
        #pragma unroll
        for (int pp = 0; pp < 16; pp++)
            yst[pp] = to_tf32(fmaf((y[pp] - mu) * r, lw[pp], lb[pp]));   // k7-only consumer
        __syncthreads();
        {
            float* gyb = g_y + (bc0 + (size_t)q * 4) * 1024;
            for (int i = t; i < 4096; i += 256) {
                int rr = i >> 10, k = i & 1023;
                gyb[rr * 1024 + k] = ystage[rr * 1088 + (k >> 4) * 17 + (k & 15)];
            }
        }
        __syncthreads();
    }
}

// ---------------- K7: tf32 mma GEMM + un-RevIN + transpose ----------------
// 321 blocks; 128 threads (4 warps); block tile 64x96; warp = 16 rows x 96 cols
__global__ void __launch_bounds__(128) k7_gemm(const float* __restrict__ rev_w,
                                               const float* __restrict__ rev_b,
                                               float* __restrict__ out) {
    __shared__ float As[2][64 * 20];
    __shared__ float Bs[2][16 * 104];
    int t = threadIdx.x;
    int w = t >> 5, lane = t & 31;
    int g = lane >> 2, tig = lane & 3;
    size_t bc0 = (size_t)blockIdx.x * 64;

    int lr = t >> 1, lk = (t & 1) * 8;               // As loader
    int bk = t >> 3, bo = (t & 7) * 12;              // Bs loader: row bk, 12 floats at bo

    uint32_t as_sm[2], bs_sm[2];
    as_sm[0] = (uint32_t)__cvta_generic_to_shared(&As[0][0]);
    as_sm[1] = (uint32_t)__cvta_generic_to_shared(&As[1][0]);
    bs_sm[0] = (uint32_t)__cvta_generic_to_shared(&Bs[0][0]);
    bs_sm[1] = (uint32_t)__cvta_generic_to_shared(&Bs[1][0]);

    float acc[12][4];
    #pragma unroll
    for (int i = 0; i < 12; i++)
        #pragma unroll
        for (int j = 0; j < 4; j++) acc[i][j] = 0.f;

    auto load_tile = [&](int it, int bu) {
        int k0 = it * 16;
        const float* srcrow;
        if (k0 < 1024) srcrow = g_y + (bc0 + lr) * 1024 + k0 + lk;
        else           srcrow = g_trend + (bc0 + lr) * 512 + (k0 - 1024) + lk;
        uint32_t d = as_sm[bu] + (uint32_t)((lr * 20 + lk) * 4);
        cpa16(d, srcrow);
        cpa16(d + 16, srcrow + 4);
        const float* bsrc = g_Wt + (k0 + bk) * 96 + bo;
        uint32_t db = bs_sm[bu] + (uint32_t)((bk * 104 + bo) * 4);
        cpa16(db, bsrc);
        cpa16(db + 16, bsrc + 4);
        cpa16(db + 32, bsrc + 8);
    };

    int ar = w * 16 + g;
    load_tile(0, 0);
    cp_commit();
    for (int it = 0; it < 96; it++) {
        int cur = it & 1;
        if (it + 1 < 96) {
            load_tile(it + 1, cur ^ 1);
            cp_commit();
            asm volatile("cp.async.wait_group 1;\n" ::: "memory");
        } else {
            asm volatile("cp.async.wait_group 0;\n" ::: "memory");
        }
        __syncthreads();
        const float* Ac = As[cur];
        const float* Bc = Bs[cur];
        #pragma unroll
        for (int kk = 0; kk < 16; kk += 8) {
            uint32_t a0 = __float_as_uint(Ac[ar * 20 + kk + tig]);
            uint32_t a1 = __float_as_uint(Ac[(ar + 8) * 20 + kk + tig]);
            uint32_t a2 = __float_as_uint(Ac[ar * 20 + kk + tig + 4]);
            uint32_t a3 = __float_as_uint(Ac[(ar + 8) * 20 + kk + tig + 4]);
            #pragma unroll
            for (int nt = 0; nt < 12; nt++) {
                uint32_t b0 = __float_as_uint(Bc[(kk + tig) * 104 + nt * 8 + g]);
                uint32_t b1 = __float_as_uint(Bc[(kk + tig + 4) * 104 + nt * 8 + g]);
                asm volatile(
                    "mma.sync.aligned.m16n8k8.row.col.f32.tf32.tf32.f32 "
                    "{%0,%1,%2,%3},{%4,%5,%6,%7},{%8,%9},{%0,%1,%2,%3};\n"
                    : "+f"(acc[nt][0]), "+f"(acc[nt][1]), "+f"(acc[nt][2]), "+f"(acc[nt][3])
                    : "r"(a0), "r"(a1), "r"(a2), "r"(a3), "r"(b0), "r"(b1));
            }
        }
        __syncthreads();
    }
    // epilogue: rows ar, ar+8; cols nt*8 + tig*2 (+1)
    size_t bcA = bc0 + ar, bcB = bc0 + ar + 8;
    int bA = (int)(bcA / C_), cA = (int)(bcA - (size_t)bA * C_);
    int bB = (int)(bcB / C_), cB = (int)(bcB - (size_t)bB * C_);
    float rwA = rev_w[cA], rbA = rev_b[cA], sdA = g_std[bcA], mnA = g_mean[bcA];
    float rwB = rev_w[cB], rbB = rev_b[cB], sdB = g_std[bcB], mnB = g_mean[bcB];
    #pragma unroll
    for (int nt = 0; nt < 12; nt++) {
        int col0 = nt * 8 + tig * 2;
        #pragma unroll
        for (int jj = 0; jj < 2; jj++) {
            int col = col0 + jj;
            float cb = g_cb[col];
            float vA = acc[nt][jj] + cb;
            vA = fmaf((vA - rbA) / rwA, sdA, mnA);
            out[((size_t)bA * PRED_ + col) * C_ + cA] = vA;
            float vB = acc[nt][2 + jj] + cb;
            vB = fmaf((vB - rbB) / rwB, sdB, mnB);
            out[((size_t)bB * PRED_ + col) * C_ + cB] = vB;
        }
    }
}

// ---------------- launch ----------------
extern "C" void kernel_launch(void* const* d_in, const int* in_sizes, int n_in,
                              void* d_out, int out_size) {
    const float* x       = (const float*)d_in[0];
    const float* rev_w   = (const float*)d_in[1];
    const float* rev_b   = (const float*)d_in[2];
    const float* fc1_w   = (const float*)d_in[3];
    const float* fc1_b   = (const float*)d_in[4];
    const float* bn1_w   = (const float*)d_in[5];
    const float* bn1_b   = (const float*)d_in[6];
    const float* conv_w  = (const float*)d_in[7];
    const float* conv_b  = (const float*)d_in[8];
    const float* bn2_w   = (const float*)d_in[9];
    const float* bn2_b   = (const float*)d_in[10];
    const float* fc2_w   = (const float*)d_in[11];
    const float* fc2_b   = (const float*)d_in[12];
    const float* m1_w    = (const float*)d_in[13];
    const float* m1_b    = (const float*)d_in[14];
    const float* m2_w    = (const float*)d_in[15];
    const float* m2_b    = (const float*)d_in[16];
    const float* gl_sc   = (const float*)d_in[17];
    const float* ln_w    = (const float*)d_in[18];
    const float* ln_b    = (const float*)d_in[19];
    const float* seas_w  = (const float*)d_in[20];
    const float* seas_b  = (const float*)d_in[21];
    const float* tr_w    = (const float*)d_in[22];
    const float* tr_b    = (const float*)d_in[23];
    const float* fus_w   = (const float*)d_in[24];
    const float* fus_b   = (const float*)d_in[25];
    float* out = (float*)d_out;

    const int K1_SMEM = 512 * 17 * 2 * sizeof(float);   // 69632
    const int KG_SMEM = 22656 * sizeof(float);           // 90624
    const int K6_SMEM = (16 * LP + 512 + 4 * 1088) * sizeof(float);
    cudaFuncSetAttribute(k1a_prep, cudaFuncAttributeMaxDynamicSharedMemorySize, K1_SMEM);
    cudaFuncSetAttribute(kg_gate, cudaFuncAttributeMaxDynamicSharedMemorySize, KG_SMEM);
    cudaFuncSetAttribute(k6_local, cudaFuncAttributeMaxDynamicSharedMemorySize, K6_SMEM);

    k0_fold1<<<384, 256>>>(seas_w, fus_w);                        // 1
    k0_fold2<<<192, 256>>>(tr_w, fus_w);                          // 2
    k0_cb<<<1, 96>>>(fus_w, fus_b, seas_b, tr_b);                 // 3
    k1a_prep<<<dim3(21, 64), 256, K1_SMEM>>>(x, rev_w, rev_b);   // 4 -> profiled
    k1b_fc1<<<NB1, 256>>>(fc1_w, fc1_b);
    k3_stats1<<<1, 1024>>>(bn1_w, bn1_b);
    k4_conv<<<NB1, 256>>>(conv_w, conv_b);
    k5_stats2<<<1, 1024>>>(bn2_w, bn2_b);
    kg_gate<<<642, 256, KG_SMEM>>>(m1_w, m1_b, m2_w, m2_b);
    k6_local<<<NB1, 256, K6_SMEM>>>(conv_w, conv_b, fc2_w, fc2_b, gl_sc, ln_w, ln_b);
    k7_gemm<<<321, 128>>>(rev_w, rev_b, out);
    (void)in_sizes; (void)n_in; (void)out_size;
}

// round 17
// speedup vs baseline: 1.3566x; 1.0588x over previous
#include <cuda_runtime.h>
#include <cuda_bf16.h>
#include <math.h>
#include <stdint.h>
#include <stddef.h>

#define B_ 64
#define L_ 512
#define C_ 321
#define BC 20544            // B_*C_
#define PRED_ 96
#define LP 520              // L + STRIDE
#define NB1 1284            // BC/16 blocks (k1b/k4/k6)
#define CNT_BN 657408.0f    // BC*32
#define EPS_ 1e-5f

// ---------------- scratch (__device__ globals; no runtime allocation) ----------------
static __device__ float g_s[(size_t)BC * LP];        // seasonal, padded
static __device__ float g_trend[(size_t)BC * L_];    // trend rows [bc][L]  (tf32-truncated)
static __device__ float g_mean[BC];
static __device__ float g_std[BC];
static __device__ float g_h[(size_t)BC * 2048];      // h1, then (after k4) gelu(conv(...)) in place
static __device__ float g_y[(size_t)BC * 1024];      // post-LN y [bc][1024]  (tf32-truncated)
static __device__ float g_pool[(size_t)BC * 64];     // sp.mean(-1)
static __device__ float g_w[(size_t)BC * 64];        // gating sigmoid output
static __device__ float g_Wt[1536 * 96];             // folded weights, [k][j]  (tf32-truncated)
static __device__ float g_cb[96];                    // folded bias (fp32 exact)
static __device__ float g_p1s[NB1 * 64];
static __device__ float g_p1q[NB1 * 64];
static __device__ float g_p2s[NB1 * 64];
static __device__ float g_p2q[NB1 * 64];
static __device__ float g_sc1[64], g_bi1[64], g_sc2[64], g_bi2[64];

__device__ __forceinline__ float geluf(float v) {
    return 0.5f * v * (1.0f + erff(v * 0.70710678f));
}
__device__ __forceinline__ float sigf(float v) {
    return 1.0f / (1.0f + expf(-v));
}
__device__ __forceinline__ float to_tf32(float v) {
    uint32_t r;
    asm("cvt.rna.tf32.f32 %0, %1;" : "=r"(r) : "f"(v));
    return __uint_as_float(r);
}

// cp.async helpers (LDGSTS)
__device__ __forceinline__ void cpa16(uint32_t d, const float* s) {
    asm volatile("cp.async.ca.shared.global [%0], [%1], 16;\n" :: "r"(d), "l"(s));
}
__device__ __forceinline__ void cp_commit() {
    asm volatile("cp.async.commit_group;\n" ::: "memory");
}

// ---------------- K0: fold fusion layer (tf32-truncated output for k7) ----------------
__global__ void k0_fold1(const float* __restrict__ seas_w, const float* __restrict__ fus_w) {
    int idx = blockIdx.x * 256 + threadIdx.x;       // 96*1024
    int j = idx >> 10, m = idx & 1023;
    const float* fw = fus_w + j * 192;
    float a = 0.f;
    #pragma unroll 8
    for (int k = 0; k < 96; k++) a = fmaf(fw[k], seas_w[k * 1024 + m], a);
    g_Wt[m * 96 + j] = to_tf32(a);
}
__global__ void k0_fold2(const float* __restrict__ tr_w, const float* __restrict__ fus_w) {
    int idx = blockIdx.x * 256 + threadIdx.x;       // 96*512
    int j = idx >> 9, m = idx & 511;
    const float* fw = fus_w + j * 192 + 96;
    float a = 0.f;
    #pragma unroll 8
    for (int k = 0; k < 96; k++) a = fmaf(fw[k], tr_w[k * 512 + m], a);
    g_Wt[(1024 + m) * 96 + j] = to_tf32(a);
}
__global__ void k0_cb(const float* __restrict__ fus_w, const float* __restrict__ fus_b,
                      const float* __restrict__ seas_b, const float* __restrict__ tr_b) {
    int j = threadIdx.x;
    float a = fus_b[j];
    for (int k = 0; k < 96; k++) {
        a = fmaf(fus_w[j * 192 + k], seas_b[k], a);
        a = fmaf(fus_w[j * 192 + 96 + k], tr_b[k], a);
    }
    g_cb[j] = a;
}

// ---------------- K1a: RevIN stats + segmented EMA + seasonal/trend + pooled ----------------
// 16 channels per block; grid (21, 64); 256 threads; dynamic smem 69632B
__global__ void __launch_bounds__(256) k1a_prep(const float* __restrict__ x,
                                                const float* __restrict__ rev_w,
                                                const float* __restrict__ rev_b) {
    extern __shared__ float sm[];
    float* xb = sm;                 // [512][17]
    float* tb = sm + 512 * 17;      // [512][17]
    __shared__ float red_s[16][17], red_q[16][17], meanb[16], stdb[16];
    __shared__ float segend[8][17], carry[8][17];
    __shared__ float pw[65];
    int b = blockIdx.y;
    int c0 = blockIdx.x * 16;
    int t = threadIdx.x;
    int w = t >> 5, lane = t & 31;
    int ci16 = t & 15, g16 = t >> 4;
    int c = c0 + ci16;
    bool cv = (c < C_);

    if (t == 0) {
        pw[0] = 1.f;
        for (int j = 1; j <= 64; j++) pw[j] = pw[j - 1] * 0.8f;
    }

    float s = 0.f, q = 0.f;
    for (int l = g16; l < L_; l += 16) {
        float v = cv ? x[((size_t)b * L_ + l) * C_ + c] : 0.f;
        xb[l * 17 + ci16] = v;
        s += v;
        q = fmaf(v, v, q);
    }
    red_s[g16][ci16] = s; red_q[g16][ci16] = q;
    __syncthreads();
    if (t < 16) {
        float ss = 0.f, qq = 0.f;
        #pragma unroll
        for (int i = 0; i < 16; i++) { ss += red_s[i][t]; qq += red_q[i][t]; }
        float mu = ss * (1.f / (float)L_);
        float v2 = fmaxf(qq - (float)L_ * mu * mu, 0.f);
        float sd = sqrtf(v2 * (1.f / (float)(L_ - 1))) + EPS_;
        meanb[t] = mu; stdb[t] = sd;
        if (c0 + t < C_) { int bc = b * C_ + c0 + t; g_mean[bc] = mu; g_std[bc] = sd; }
    }
    __syncthreads();
    {
        float rw = cv ? rev_w[c] : 1.f;
        float rb = cv ? rev_b[c] : 0.f;
        float mu = meanb[ci16], inv = 1.f / stdb[ci16];
        for (int l = g16; l < L_; l += 16) {
            float v = xb[l * 17 + ci16];
            xb[l * 17 + ci16] = fmaf((v - mu) * inv, rw, rb);
        }
    }
    __syncthreads();
    if (t < 128) {
        int seg = t >> 4;
        int base = seg * 64;
        float cl;
        if (seg == 0) {
            cl = xb[ci16];
            tb[ci16] = cl;
            #pragma unroll 4
            for (int l = 1; l < 64; l++) {
                cl = fmaf(0.8f, cl, 0.2f * xb[l * 17 + ci16]);
                tb[l * 17 + ci16] = cl;
            }
        } else {
            cl = 0.f;
            #pragma unroll 4
            for (int j = 0; j < 64; j++) {
                int l = base + j;
                cl = fmaf(0.8f, cl, 0.2f * xb[l * 17 + ci16]);
                tb[l * 17 + ci16] = cl;
            }
        }
        segend[seg][ci16] = cl;
    }
    __syncthreads();
    if (t < 16) {
        float cacc = segend[0][t];
        carry[1][t] = cacc;
        float q64 = pw[64];
        #pragma unroll
        for (int s2 = 1; s2 <= 6; s2++) {
            cacc = fmaf(q64, cacc, segend[s2][t]);
            carry[s2 + 1][t] = cacc;
        }
    }
    __syncthreads();
    if (t < 128) {
        int seg = t >> 4;
        int base = seg * 64;
        float cin = (seg == 0) ? 0.f : carry[seg][ci16];
        #pragma unroll 4
        for (int j = 0; j < 64; j++) {
            int l = base + j;
            float tf = fmaf(pw[j + 1], cin, tb[l * 17 + ci16]);
            tb[l * 17 + ci16] = tf;
            xb[l * 17 + ci16] = xb[l * 17 + ci16] - tf;
        }
    }
    __syncthreads();
    for (int ci = w; ci < 16; ci += 8) {
        int cc = c0 + ci;
        if (cc >= C_) continue;
        size_t bc = (size_t)b * C_ + cc;
        float* gs = g_s + bc * LP;
        float* gt = g_trend + bc * (size_t)L_;
        for (int l0 = 0; l0 < L_; l0 += 32) {
            gs[l0 + lane] = xb[(l0 + lane) * 17 + ci];
            gt[l0 + lane] = to_tf32(tb[(l0 + lane) * 17 + ci]);   // k7-only consumer
        }
        if (lane < 8) gs[L_ + lane] = xb[511 * 17 + ci];
        #pragma unroll
        for (int nn = 0; nn < 2; nn++) {
            int n = 2 * lane + nn;
            float sum = 0.f;
            #pragma unroll
            for (int p = 0; p < 16; p++) {
                int l = n * 8 + p;
                if (l > 511) l = 511;
                sum += xb[l * 17 + ci];
            }
            g_pool[bc * 64 + n] = sum * (1.f / 16.f);
        }
    }
}

// ---------------- K1b: fc1 + gelu -> g_h ([bc][j][n]); bn1 per-n partials ----------------
__global__ void __launch_bounds__(256) k1b_fc1(const float* __restrict__ fc1_w,
                                               const float* __restrict__ fc1_b) {
    __shared__ float s_sm[16 * LP];
    __shared__ float wt[512];
    __shared__ float stage[32 * 65];
    int t = threadIdx.x;
    int w = t >> 5, lane = t & 31;
    size_t bc0 = (size_t)blockIdx.x * 16;
    for (int i = t; i < 512; i += 256) {
        int p = i >> 5, j = i & 31;
        wt[i] = fc1_w[j * 16 + p];
    }
    for (int i = t; i < 16 * LP; i += 256) s_sm[i] = g_s[bc0 * LP + i];
    __syncthreads();
    float wj[16];
    #pragma unroll
    for (int p = 0; p < 16; p++) wj[p] = wt[p * 32 + lane];
    float bj = fc1_b[lane];
    float ps[8], pq[8];
    #pragma unroll
    for (int i = 0; i < 8; i++) { ps[i] = 0.f; pq[i] = 0.f; }

    for (int r = 0; r < 16; r++) {
        const float* sp = s_sm + r * LP;
        #pragma unroll
        for (int nn = 0; nn < 8; nn++) {
            int n = nn * 8 + w;
            const float4* pv4 = (const float4*)(sp + n * 8);
            float4 f0 = pv4[0], f1 = pv4[1], f2 = pv4[2], f3 = pv4[3];
            float acc = bj;
            acc = fmaf(f0.x, wj[0], acc);
            acc = fmaf(f0.y, wj[1], acc);
            acc = fmaf(f0.z, wj[2], acc);
            acc = fmaf(f0.w, wj[3], acc);
            acc = fmaf(f1.x, wj[4], acc);
            acc = fmaf(f1.y, wj[5], acc);
            acc = fmaf(f1.z, wj[6], acc);
            acc = fmaf(f1.w, wj[7], acc);
            acc = fmaf(f2.x, wj[8], acc);
            acc = fmaf(f2.y, wj[9], acc);
            acc = fmaf(f2.z, wj[10], acc);
            acc = fmaf(f2.w, wj[11], acc);
            acc = fmaf(f3.x, wj[12], acc);
            acc = fmaf(f3.y, wj[13], acc);
            acc = fmaf(f3.z, wj[14], acc);
            acc = fmaf(f3.w, wj[15], acc);
            float g = geluf(acc);
            ps[nn] += g;
            pq[nn] = fmaf(g, g, pq[nn]);
            stage[lane * 65 + n] = g;
        }
        __syncthreads();
        float* dst = g_h + (bc0 + r) * 2048;
        for (int i = t; i < 2048; i += 256)
            dst[i] = stage[(i >> 6) * 65 + (i & 63)];
        __syncthreads();
    }
    #pragma unroll
    for (int nn = 0; nn < 8; nn++) {
        float s = ps[nn], q = pq[nn];
        #pragma unroll
        for (int off = 16; off; off >>= 1) {
            s += __shfl_down_sync(0xffffffff, s, off);
            q += __shfl_down_sync(0xffffffff, q, off);
        }
        if (lane == 0) {
            int n = nn * 8 + w;
            g_p1s[blockIdx.x * 64 + n] = s;
            g_p1q[blockIdx.x * 64 + n] = q;
        }
    }
}

// ---------------- K3/K5: reduce bn partials ----------------
__global__ void __launch_bounds__(1024) k3_stats1(const float* __restrict__ bn_w,
                                                  const float* __restrict__ bn_b) {
    __shared__ float ss[1024], qq[1024];
    int t = threadIdx.x;
    int n = t & 63, part = t >> 6;
    float s = 0.f, q = 0.f;
    for (int blk = part; blk < NB1; blk += 16) { s += g_p1s[blk * 64 + n]; q += g_p1q[blk * 64 + n]; }
    ss[t] = s; qq[t] = q;
    __syncthreads();
    if (t < 64) {
        float S = 0.f, Q = 0.f;
        #pragma unroll
        for (int i = 0; i < 16; i++) { S += ss[t + 64 * i]; Q += qq[t + 64 * i]; }
        float inv = 1.f / CNT_BN;
        float mu = S * inv;
        float var = fmaxf(Q * inv - mu * mu, 0.f);
        float sc = bn_w[t] * rsqrtf(var + EPS_);
        g_sc1[t] = sc;
        g_bi1[t] = fmaf(-mu, sc, bn_b[t]);
    }
}
__global__ void __launch_bounds__(1024) k5_stats2(const float* __restrict__ bn_w,
                                                  const float* __restrict__ bn_b) {
    __shared__ float ss[1024], qq[1024];
    int t = threadIdx.x;
    int n = t & 63, part = t >> 6;
    float s = 0.f, q = 0.f;
    for (int blk = part; blk < NB1; blk += 16) { s += g_p2s[blk * 64 + n]; q += g_p2q[blk * 64 + n]; }
    ss[t] = s; qq[t] = q;
    __syncthreads();
    if (t < 64) {
        float S = 0.f, Q = 0.f;
        #pragma unroll
        for (int i = 0; i < 16; i++) { S += ss[t + 64 * i]; Q += qq[t + 64 * i]; }
        float inv = 1.f / CNT_BN;
        float mu = S * inv;
        float var = fmaxf(Q * inv - mu * mu, 0.f);
        float sc = bn_w[t] * rsqrtf(var + EPS_);
        g_sc2[t] = sc;
        g_bi2[t] = fmaf(-mu, sc, bn_b[t]);
    }
}

// ---------------- K4: g_h <- gelu(conv(bn1_affine(g_h))) in place; bn2 partials ----------------
__global__ void __launch_bounds__(256) k4_conv(const float* __restrict__ conv_w,
                                               const float* __restrict__ conv_b) {
    __shared__ float rs[256], rq[256];
    int t = threadIdx.x;
    size_t bc0 = (size_t)blockIdx.x * 16;
    int n = t & 63;
    float sc = g_sc1[n], bi = g_bi1[n];
    float c0 = conv_w[n * 3], c1 = conv_w[n * 3 + 1], c2 = conv_w[n * 3 + 2];
    float cbv = conv_b[n];
    float psum = 0.f, psq = 0.f;
    #pragma unroll
    for (int q = 0; q < 4; q++) {
        int pair = t + 256 * q;
        int row = pair >> 6;
        float* hp = g_h + (bc0 + row) * 2048 + n;
        float a[34];
        a[0] = 0.f; a[33] = 0.f;
        #pragma unroll
        for (int j = 0; j < 32; j++) a[j + 1] = fmaf(hp[j * 64], sc, bi);
        #pragma unroll
        for (int j = 0; j < 32; j++) {
            float vv = cbv;
            vv = fmaf(a[j], c0, vv);
            vv = fmaf(a[j + 1], c1, vv);
            vv = fmaf(a[j + 2], c2, vv);
            float g = geluf(vv);
            hp[j * 64] = g;                 // write back for k6 (no recompute there)
            psum += g;
            psq = fmaf(g, g, psq);
        }
    }
    rs[t] = psum; rq[t] = psq;
    __syncthreads();
    if (t < 64) {
        float S = rs[t] + rs[t + 64] + rs[t + 128] + rs[t + 192];
        float Q = rq[t] + rq[t + 64] + rq[t + 128] + rq[t + 192];
        g_p2s[blockIdx.x * 64 + t] = S;
        g_p2q[blockIdx.x * 64 + t] = Q;
    }
}

// ---------------- Kg: gating MLP, 4 rows/warp batched ----------------
__global__ void __launch_bounds__(256) kg_gate(const float* __restrict__ m1_w,
                                               const float* __restrict__ m1_b,
                                               const float* __restrict__ m2_w,
                                               const float* __restrict__ m2_b) {
    extern __shared__ float kg_sm[];
    float* m1p = kg_sm;                 // 8320
    float* m2t = kg_sm + 8320;          // 8192
    float* ps  = kg_sm + 16512;         // 2048
    float* us  = kg_sm + 18560;         // 4096
    int t = threadIdx.x;
    int w = t >> 5, lane = t & 31;
    size_t bc0 = (size_t)blockIdx.x * 32;
    for (int i = t; i < 8192; i += 256) {
        int h = i >> 6, k = i & 63;
        m1p[h * 65 + k] = m1_w[i];
    }
    for (int i = t; i < 8192; i += 256) {
        int nn = i >> 7, h = i & 127;
        m2t[h * 64 + nn] = m2_w[i];
    }
    for (int i = t; i < 2048; i += 256)
        ps[i] = g_pool[bc0 * 64 + i];
    __syncthreads();
    int r0 = w * 4;
    float u[4][4];
    {
        float b0 = m1_b[lane], b1 = m1_b[lane + 32], b2 = m1_b[lane + 64], b3 = m1_b[lane + 96];
        #pragma unroll
        for (int r = 0; r < 4; r++) { u[r][0] = b0; u[r][1] = b1; u[r][2] = b2; u[r][3] = b3; }
    }
    #pragma unroll 4
    for (int k = 0; k < 64; k++) {
        float wv0 = m1p[lane * 65 + k];
        float wv1 = m1p[(lane + 32) * 65 + k];
        float wv2 = m1p[(lane + 64) * 65 + k];
        float wv3 = m1p[(lane + 96) * 65 + k];
        #pragma unroll
        for (int r = 0; r < 4; r++) {
            float pk = ps[(r0 + r) * 64 + k];
            u[r][0] = fmaf(pk, wv0, u[r][0]);
            u[r][1] = fmaf(pk, wv1, u[r][1]);
            u[r][2] = fmaf(pk, wv2, u[r][2]);
            u[r][3] = fmaf(pk, wv3, u[r][3]);
        }
    }
    #pragma unroll
    for (int r = 0; r < 4; r++) {
        float* uwr = us + (r0 + r) * 128;
        uwr[lane] = geluf(u[r][0]);
        uwr[lane + 32] = geluf(u[r][1]);
        uwr[lane + 64] = geluf(u[r][2]);
        uwr[lane + 96] = geluf(u[r][3]);
    }
    __syncwarp();
    float acc[4][2];
    {
        float b0 = m2_b[lane], b1 = m2_b[lane + 32];
        #pragma unroll
        for (int r = 0; r < 4; r++) { acc[r][0] = b0; acc[r][1] = b1; }
    }
    #pragma unroll 4
    for (int h = 0; h < 128; h++) {
        float w0 = m2t[h * 64 + lane];
        float w1 = m2t[h * 64 + lane + 32];
        #pragma unroll
        for (int r = 0; r < 4; r++) {
            float uh = us[(r0 + r) * 128 + h];
            acc[r][0] = fmaf(uh, w0, acc[r][0]);
            acc[r][1] = fmaf(uh, w1, acc[r][1]);
        }
    }
    #pragma unroll
    for (int r = 0; r < 4; r++) {
        g_w[(bc0 + r0 + r) * 64 + lane] = sigf(acc[r][0]);
        g_w[(bc0 + r0 + r) * 64 + lane + 32] = sigf(acc[r][1]);
    }
}

// ---------------- K6: read conv output from g_h, bn2 affine + fc2 + combine + LN -> g_y ----------------
__global__ void __launch_bounds__(256) k6_local(const float* __restrict__ fc2_w,
                                                const float* __restrict__ fc2_b,
                                                const float* __restrict__ gl_scale,
                                                const float* __restrict__ ln_w,
                                                const float* __restrict__ ln_b) {
    extern __shared__ float k6_sm[];
    float* s_sm = k6_sm;                       // 8320 floats
    float* w2 = k6_sm + 16 * LP;               // 512
    float* ystage = k6_sm + 16 * LP + 512;     // 4*1088
    __shared__ float b2[16], lw[16], lb[16];
    int t = threadIdx.x;
    size_t bc0 = (size_t)blockIdx.x * 16;
    w2[t] = fc2_w[t];
    w2[t + 256] = fc2_w[t + 256];
    if (t < 16) { b2[t] = fc2_b[t]; lw[t] = ln_w[t]; lb[t] = ln_b[t]; }
    for (int i = t; i < 16 * LP; i += 256) s_sm[i] = g_s[bc0 * LP + i];
    __syncthreads();
    float gs = gl_scale[0];
    int n = t & 63;
    float sc2v = g_sc2[n], bi2v = g_bi2[n];
    #pragma unroll
    for (int q = 0; q < 4; q++) {
        int pair = t + 256 * q;
        int row = pair >> 6;
        int r4 = row & 3;
        size_t bc = bc0 + row;
        const float* hp = g_h + bc * 2048 + n;
        float h2[32];
        #pragma unroll
        for (int j = 0; j < 32; j++) h2[j] = fmaf(hp[j * 64], sc2v, bi2v);
        float p[16];
        const float4* spp = (const float4*)(s_sm + row * LP + n * 8);
        #pragma unroll
        for (int v = 0; v < 4; v++) {
            float4 f = spp[v];
            p[4 * v] = f.x; p[4 * v + 1] = f.y; p[4 * v + 2] = f.z; p[4 * v + 3] = f.w;
        }
        float wv = g_w[bc * 64 + n];
        float m3 = fmaf(gs, wv, 3.f);
        float y[16];
        float musum = 0.f;
        #pragma unroll
        for (int pp = 0; pp < 16; pp++) {
            float acc = b2[pp];
            const float4* wp = (const float4*)(w2 + pp * 32);
            #pragma unroll
            for (int j = 0; j < 8; j++) {
                float4 f = wp[j];
                acc = fmaf(h2[4 * j], f.x, acc);
                acc = fmaf(h2[4 * j + 1], f.y, acc);
                acc = fmaf(h2[4 * j + 2], f.z, acc);
                acc = fmaf(h2[4 * j + 3], f.w, acc);
            }
            float yy = fmaf(p[pp], m3, acc);
            y[pp] = yy;
            musum += yy;
        }
        float mu = musum * (1.f / 16.f);
        float s2 = 0.f;
        #pragma unroll
        for (int pp = 0; pp < 16; pp++) { float d = y[pp] - mu; s2 = fmaf(d, d, s2); }
        float r = rsqrtf(s2 * (1.f / 16.f) + EPS_);
        float* yst = ystage + r4 * 1088 + n * 17;
        #pragma unroll
        for (int pp = 0; pp < 16; pp++)
            yst[pp] = to_tf32(fmaf((y[pp] - mu) * r, lw[pp], lb[pp]));   // k7-only consumer
        __syncthreads();
        {
            float* gyb = g_y + (bc0 + (size_t)q * 4) * 1024;
            for (int i = t; i < 4096; i += 256) {
                int rr = i >> 10, k = i & 1023;
                gyb[rr * 1024 + k] = ystage[rr * 1088 + (k >> 4) * 17 + (k & 15)];
            }
        }
        __syncthreads();
    }
}

// ---------------- K7: tf32 mma GEMM + un-RevIN + transpose ----------------
// 321 blocks; 128 threads (4 warps); block tile 64x96; warp = 16 rows x 96 cols
__global__ void __launch_bounds__(128) k7_gemm(const float* __restrict__ rev_w,
                                               const float* __restrict__ rev_b,
                                               float* __restrict__ out) {
    __shared__ float As[2][64 * 20];
    __shared__ float Bs[2][16 * 104];
    int t = threadIdx.x;
    int w = t >> 5, lane = t & 31;
    int g = lane >> 2, tig = lane & 3;
    size_t bc0 = (size_t)blockIdx.x * 64;

    int lr = t >> 1, lk = (t & 1) * 8;               // As loader
    int bk = t >> 3, bo = (t & 7) * 12;              // Bs loader

    uint32_t as_sm[2], bs_sm[2];
    as_sm[0] = (uint32_t)__cvta_generic_to_shared(&As[0][0]);
    as_sm[1] = (uint32_t)__cvta_generic_to_shared(&As[1][0]);
    bs_sm[0] = (uint32_t)__cvta_generic_to_shared(&Bs[0][0]);
    bs_sm[1] = (uint32_t)__cvta_generic_to_shared(&Bs[1][0]);

    float acc[12][4];
    #pragma unroll
    for (int i = 0; i < 12; i++)
        #pragma unroll
        for (int j = 0; j < 4; j++) acc[i][j] = 0.f;

    auto load_tile = [&](int it, int bu) {
        int k0 = it * 16;
        const float* srcrow;
        if (k0 < 1024) srcrow = g_y + (bc0 + lr) * 1024 + k0 + lk;
        else           srcrow = g_trend + (bc0 + lr) * 512 + (k0 - 1024) + lk;
        uint32_t d = as_sm[bu] + (uint32_t)((lr * 20 + lk) * 4);
        cpa16(d, srcrow);
        cpa16(d + 16, srcrow + 4);
        const float* bsrc = g_Wt + (k0 + bk) * 96 + bo;
        uint32_t db = bs_sm[bu] + (uint32_t)((bk * 104 + bo) * 4);
        cpa16(db, bsrc);
        cpa16(db + 16, bsrc + 4);
        cpa16(db + 32, bsrc + 8);
    };

    int ar = w * 16 + g;
    load_tile(0, 0);
    cp_commit();
    for (int it = 0; it < 96; it++) {
        int cur = it & 1;
        if (it + 1 < 96) {
            load_tile(it + 1, cur ^ 1);
            cp_commit();
            asm volatile("cp.async.wait_group 1;\n" ::: "memory");
        } else {
            asm volatile("cp.async.wait_group 0;\n" ::: "memory");
        }
        __syncthreads();
        const float* Ac = As[cur];
        const float* Bc = Bs[cur];
        #pragma unroll
        for (int kk = 0; kk < 16; kk += 8) {
            uint32_t a0 = __float_as_uint(Ac[ar * 20 + kk + tig]);
            uint32_t a1 = __float_as_uint(Ac[(ar + 8) * 20 + kk + tig]);
            uint32_t a2 = __float_as_uint(Ac[ar * 20 + kk + tig + 4]);
            uint32_t a3 = __float_as_uint(Ac[(ar + 8) * 20 + kk + tig + 4]);
            #pragma unroll
            for (int nt = 0; nt < 12; nt++) {
                uint32_t b0 = __float_as_uint(Bc[(kk + tig) * 104 + nt * 8 + g]);
                uint32_t b1 = __float_as_uint(Bc[(kk + tig + 4) * 104 + nt * 8 + g]);
                asm volatile(
                    "mma.sync.aligned.m16n8k8.row.col.f32.tf32.tf32.f32 "
                    "{%0,%1,%2,%3},{%4,%5,%6,%7},{%8,%9},{%0,%1,%2,%3};\n"
                    : "+f"(acc[nt][0]), "+f"(acc[nt][1]), "+f"(acc[nt][2]), "+f"(acc[nt][3])
                    : "r"(a0), "r"(a1), "r"(a2), "r"(a3), "r"(b0), "r"(b1));
            }
        }
        __syncthreads();
    }
    size_t bcA = bc0 + ar, bcB = bc0 + ar + 8;
    int bA = (int)(bcA / C_), cA = (int)(bcA - (size_t)bA * C_);
    int bB = (int)(bcB / C_), cB = (int)(bcB - (size_t)bB * C_);
    float rwA = rev_w[cA], rbA = rev_b[cA], sdA = g_std[bcA], mnA = g_mean[bcA];
    float rwB = rev_w[cB], rbB = rev_b[cB], sdB = g_std[bcB], mnB = g_mean[bcB];
    #pragma unroll
    for (int nt = 0; nt < 12; nt++) {
        int col0 = nt * 8 + tig * 2;
        #pragma unroll
        for (int jj = 0; jj < 2; jj++) {
            int col = col0 + jj;
            float cb = g_cb[col];
            float vA = acc[nt][jj] + cb;
            vA = fmaf((vA - rbA) / rwA, sdA, mnA);
            out[((size_t)bA * PRED_ + col) * C_ + cA] = vA;
            float vB = acc[nt][2 + jj] + cb;
            vB = fmaf((vB - rbB) / rwB, sdB, mnB);
            out[((size_t)bB * PRED_ + col) * C_ + cB] = vB;
        }
    }
}

// ---------------- launch ----------------
extern "C" void kernel_launch(void* const* d_in, const int* in_sizes, int n_in,
                              void* d_out, int out_size) {
    const float* x       = (const float*)d_in[0];
    const float* rev_w   = (const float*)d_in[1];
    const float* rev_b   = (const float*)d_in[2];
    const float* fc1_w   = (const float*)d_in[3];
    const float* fc1_b   = (const float*)d_in[4];
    const float* bn1_w   = (const float*)d_in[5];
    const float* bn1_b   = (const float*)d_in[6];
    const float* conv_w  = (const float*)d_in[7];
    const float* conv_b  = (const float*)d_in[8];
    const float* bn2_w   = (const float*)d_in[9];
    const float* bn2_b   = (const float*)d_in[10];
    const float* fc2_w   = (const float*)d_in[11];
    const float* fc2_b   = (const float*)d_in[12];
    const float* m1_w    = (const float*)d_in[13];
    const float* m1_b    = (const float*)d_in[14];
    const float* m2_w    = (const float*)d_in[15];
    const float* m2_b    = (const float*)d_in[16];
    const float* gl_sc   = (const float*)d_in[17];
    const float* ln_w    = (const float*)d_in[18];
    const float* ln_b    = (const float*)d_in[19];
    const float* seas_w  = (const float*)d_in[20];
    const float* seas_b  = (const float*)d_in[21];
    const float* tr_w    = (const float*)d_in[22];
    const float* tr_b    = (const float*)d_in[23];
    const float* fus_w   = (const float*)d_in[24];
    const float* fus_b   = (const float*)d_in[25];
    float* out = (float*)d_out;

    const int K1_SMEM = 512 * 17 * 2 * sizeof(float);   // 69632
    const int KG_SMEM = 22656 * sizeof(float);           // 90624
    const int K6_SMEM = (16 * LP + 512 + 4 * 1088) * sizeof(float);
    cudaFuncSetAttribute(k1a_prep, cudaFuncAttributeMaxDynamicSharedMemorySize, K1_SMEM);
    cudaFuncSetAttribute(kg_gate, cudaFuncAttributeMaxDynamicSharedMemorySize, KG_SMEM);
    cudaFuncSetAttribute(k6_local, cudaFuncAttributeMaxDynamicSharedMemorySize, K6_SMEM);

    k0_fold1<<<384, 256>>>(seas_w, fus_w);                        // 1
    k0_fold2<<<192, 256>>>(tr_w, fus_w);                          // 2
    k0_cb<<<1, 96>>>(fus_w, fus_b, seas_b, tr_b);                 // 3
    k1a_prep<<<dim3(21, 64), 256, K1_SMEM>>>(x, rev_w, rev_b);   // 4 -> profiled
    k1b_fc1<<<NB1, 256>>>(fc1_w, fc1_b);
    k3_stats1<<<1, 1024>>>(bn1_w, bn1_b);
    k4_conv<<<NB1, 256>>>(conv_w, conv_b);
    k5_stats2<<<1, 1024>>>(bn2_w, bn2_b);
    kg_gate<<<642, 256, KG_SMEM>>>(m1_w, m1_b, m2_w, m2_b);
    k6_local<<<NB1, 256, K6_SMEM>>>(fc2_w, fc2_b, gl_sc, ln_w, ln_b);
    k7_gemm<<<321, 128>>>(rev_w, rev_b, out);
    (void)in_sizes; (void)n_in; (void)out_size;
}